// round 14
// baseline (speedup 1.0000x reference)
#include <cuda_runtime.h>
#include <cstdint>

#define BB   16
#define NN   4096
#define CIN  64
#define COUT 128
#define MM   1024
#define KNB  16
#define RR   (BB*MM*KNB)      // 262144 rows
#define LDF  68               // rel(3) + pad(1) + x(64)
#define EPSV 1e-5f
typedef unsigned long long ull;

// ---- packed f32x2 helpers --------------------------------------------------
#define PACK2(out, lo, hi)  asm("mov.b64 %0, {%1, %2};" : "=l"(out) : "f"(lo), "f"(hi))
#define UNPACK2(lo, hi, in) asm("mov.b64 {%0, %1}, %2;" : "=f"(lo), "=f"(hi) : "l"(in))
#define FMA2(acc, a, b)     asm("fma.rn.f32x2 %0, %1, %2, %3;" : "=l"(acc) : "l"(a), "l"(b), "l"(acc))
#define FMA2O(out, a, b, c) asm("fma.rn.f32x2 %0, %1, %2, %3;" : "=l"(out) : "l"(a), "l"(b), "l"(c))
#define ADD2(out, a, b)     asm("add.rn.f32x2 %0, %1, %2;" : "=l"(out) : "l"(a), "l"(b))
#define MUL2(out, a, b)     asm("mul.rn.f32x2 %0, %1, %2;" : "=l"(out) : "l"(a), "l"(b))

// ---------------- scratch (device globals; no allocation allowed) ----------
__device__ float d_xt[(size_t)BB*NN*CIN];        // 16 MB  x1 transposed [B,N,C]
__device__ float d_p2[(size_t)BB*MM*3];          // sampled centers
__device__ int   d_knn[(size_t)BB*MM*KNB];       // knn indices (global point idx)
__device__ float d_cd[(size_t)BB*MM*128];        // knn candidate dists (8 chunks x 16)
__device__ int   d_ci[(size_t)BB*MM*128];        // knn candidate idx
__device__ float d_h1[(size_t)RR*COUT];          // 134 MB
__device__ float d_mx[(size_t)BB*MM*COUT];       // 8 MB  per-(b,m) max of h2
__device__ float d_s1[2*COUT];                   // layer1 sum / sumsq
__device__ float d_s2[2*COUT];                   // layer2 sum / sumsq

// ---------------- FPS (blocks 0..15) + x1 transpose (blocks 16..) ----------
#define FPS_SMEM (192 + 3*NN*4 + MM*4)
__global__ void __launch_bounds__(512,1) fps_tr_kernel(const float* __restrict__ p1,
                                                       const float* __restrict__ x1,
                                                       float* __restrict__ out_p2)
{
    extern __shared__ char sraw[];
    const int tid = threadIdx.x;

    if (blockIdx.x >= BB) {
        // ---- transpose tile: [B,C,N] -> [B,N,C] ----
        float (*t)[33] = (float (*)[33])sraw;
        int tI = blockIdx.x - BB;
        if (tI == 0 && tid < 2*COUT) {        // fold stat zeroing in (runs before gemm1)
            d_s1[tid] = 0.f; d_s2[tid] = 0.f;
        }
        int b   = tI >> 8;
        int rem = tI & 255;
        int c0  = (rem >> 7) << 5;       // 0 or 32
        int n0  = (rem & 127) << 5;
        int tx = tid & 31, ty = tid >> 5;    // ty 0..15
        #pragma unroll
        for (int i = 0; i < 32; i += 16)
            t[ty+i][tx] = x1[((size_t)b*CIN + c0+ty+i)*NN + n0 + tx];
        __syncthreads();
        #pragma unroll
        for (int i = 0; i < 32; i += 16)
            d_xt[((size_t)b*NN + n0+ty+i)*CIN + c0 + tx] = t[tx][ty+i];
        return;
    }

    // ---- FPS: 512 threads, 8 points/thread (4 packed pairs) ----
    ull*   wkey = (ull*)sraw;                 // 16 per-warp keys
    float* px = (float*)(sraw + 192);
    float* py = px + NN;
    float* pz = py + NN;
    int*   sidx = (int*)(pz + NN);

    const int b = blockIdx.x;
    const int lane = tid & 31, wid = tid >> 5;
    const float* pb = p1 + (size_t)b*NN*3;

    for (int i = tid; i < NN; i += 512) {
        px[i] = pb[3*i+0]; py[i] = pb[3*i+1]; pz[i] = pb[3*i+2];
    }
    __syncthreads();

    ull rx2[4], ry2[4], rz2[4];
    float dist[8];
    #pragma unroll
    for (int pp = 0; pp < 4; pp++) {
        int j0 = tid + ((2*pp  ) << 9);
        int j1 = tid + ((2*pp+1) << 9);
        PACK2(rx2[pp], px[j0], px[j1]);
        PACK2(ry2[pp], py[j0], py[j1]);
        PACK2(rz2[pp], pz[j0], pz[j1]);
        dist[2*pp] = 1e10f; dist[2*pp+1] = 1e10f;
    }

    int far = 0;
    for (int it = 0; it < MM; ++it) {
        if (tid == 0) sidx[it] = far;
        float cx = px[far], cy = py[far], cz = pz[far];
        ull ncx2, ncy2, ncz2;
        { float nx = -cx, ny = -cy, nz = -cz;
          PACK2(ncx2, nx, nx); PACK2(ncy2, ny, ny); PACK2(ncz2, nz, nz); }

        #pragma unroll
        for (int pp = 0; pp < 4; pp++) {
            ull dx, dy, dz, dd;
            ADD2(dx, rx2[pp], ncx2);
            ADD2(dy, ry2[pp], ncy2);
            ADD2(dz, rz2[pp], ncz2);
            MUL2(dd, dz, dz);
            FMA2(dd, dy, dy);
            FMA2(dd, dx, dx);
            float d0, d1; UNPACK2(d0, d1, dd);
            dist[2*pp]   = fminf(dist[2*pp],   d0);
            dist[2*pp+1] = fminf(dist[2*pp+1], d1);
        }

        // per-thread argmax (first-index tie-break: earlier q wins)
        float bd = dist[0]; int bi = tid;
        #pragma unroll
        for (int q = 1; q < 8; q++)
            if (dist[q] > bd) { bd = dist[q]; bi = tid + (q<<9); }

        unsigned bku = __float_as_uint(bd);
        unsigned mk  = __reduce_max_sync(0xffffffffu, bku);
        unsigned cnd = (bku == mk) ? (unsigned)bi : 0xffffffffu;
        unsigned mi  = __reduce_min_sync(0xffffffffu, cnd);
        if (lane == 0)
            wkey[wid] = ((ull)mk << 32) | (unsigned)(~mi);
        __syncthreads();

        // cross-warp: every warp reduces the 16 keys (4-level u64 shfl tree)
        ull k = wkey[lane & 15];
        #pragma unroll
        for (int off = 8; off > 0; off >>= 1) {
            ull o = __shfl_xor_sync(0xffffffffu, k, off);
            if (o > k) k = o;
        }
        far = (int)(~(unsigned)k);
    }
    __syncthreads();
    for (int m = tid; m < MM; m += 512) {
        int j = sidx[m];
        float x = px[j], y = py[j], z = pz[j];
        size_t o = ((size_t)b*MM + m)*3;
        d_p2[o+0] = x; d_p2[o+1] = y; d_p2[o+2] = z;
        out_p2[o+0] = x; out_p2[o+1] = y; out_p2[o+2] = z;
    }
}

// ---------------- KNN part: top-16 within a 512-point chunk, 2 queries/thr --
#define NCHK 512
#define KNN_SMEM (NCHK*32)

#define KNN_INSERT(d2v, idv, bd, bi)                                   \
    if ((d2v) < bd[KNB-1]) {                                           \
        bd[KNB-1] = (d2v); bi[KNB-1] = (idv);                          \
        _Pragma("unroll")                                              \
        for (int t = KNB-1; t > 0; --t) {                              \
            if (bd[t] < bd[t-1]) {                                     \
                float td = bd[t]; bd[t] = bd[t-1]; bd[t-1] = td;       \
                int   ti = bi[t]; bi[t] = bi[t-1]; bi[t-1] = ti;       \
            }                                                          \
        }                                                              \
    }

__global__ void __launch_bounds__(256) knn_part_kernel(const float* __restrict__ p1)
{
    extern __shared__ ull pn2[];           // [NCHK][4] : (xx, yy, zz, ww)
    const int b = blockIdx.y, tid = threadIdx.x;
    const int ch = blockIdx.x & 7;            // point chunk (0..7)
    const int qg = blockIdx.x >> 3;           // query group (0..1)
    const float* pb = p1 + (size_t)b*NN*3;

    for (int i = tid; i < NCHK; i += 256) {
        int g = ch*NCHK + i;
        float x = pb[3*g], y = pb[3*g+1], z = pb[3*g+2];
        float n1 = (x*x + y*y) + z*z;
        if (x == 0.f && y == 0.f && z == 0.f) n1 = __int_as_float(0x7f800000);
        ull xx, yy, zz, ww;
        PACK2(xx, x, x); PACK2(yy, y, y); PACK2(zz, z, z); PACK2(ww, n1, n1);
        pn2[i*4+0] = xx; pn2[i*4+1] = yy; pn2[i*4+2] = zz; pn2[i*4+3] = ww;
    }
    __syncthreads();

    const int m0 = qg*512 + tid;
    const int m1 = m0 + 256;
    size_t q0o = ((size_t)b*MM + m0)*3;
    size_t q1o = ((size_t)b*MM + m1)*3;
    float q0x = d_p2[q0o], q0y = d_p2[q0o+1], q0z = d_p2[q0o+2];
    float q1x = d_p2[q1o], q1y = d_p2[q1o+1], q1z = d_p2[q1o+2];
    float n20 = (q0x*q0x + q0y*q0y) + q0z*q0z;
    float n21 = (q1x*q1x + q1y*q1y) + q1z*q1z;

    ull qx01, qy01, qz01, n201, m2d;
    PACK2(qx01, q0x, q1x); PACK2(qy01, q0y, q1y); PACK2(qz01, q0z, q1z);
    PACK2(n201, n20, n21);
    { float m2 = -2.f; PACK2(m2d, m2, m2); }

    float bd0[KNB], bd1[KNB]; int bi0[KNB], bi1[KNB];
    #pragma unroll
    for (int t = 0; t < KNB; t++) {
        bd0[t] = 3.4e38f; bi0[t] = 0;
        bd1[t] = 3.4e38f; bi1[t] = 0;
    }

    #pragma unroll 4
    for (int j = 0; j < NCHK; j++) {
        const ulonglong2* pj = (const ulonglong2*)&pn2[j*4];
        ulonglong2 a = pj[0];                 // (xx, yy)
        ulonglong2 c = pj[1];                 // (zz, ww)
        int id = ch*NCHK + j;
        ull dot, t01, d01;
        MUL2(dot, qx01, a.x);
        FMA2(dot, qy01, a.y);
        FMA2(dot, qz01, c.x);
        ADD2(t01, n201, c.y);                 // n2 + n1
        FMA2O(d01, m2d, dot, t01);            // d2 = n2+n1 - 2 dot
        float d20, d21; UNPACK2(d20, d21, d01);
        KNN_INSERT(d20, id, bd0, bi0);
        KNN_INSERT(d21, id, bd1, bi1);
    }
    size_t base0 = ((size_t)b*MM + m0)*128 + ch*16;
    size_t base1 = ((size_t)b*MM + m1)*128 + ch*16;
    #pragma unroll
    for (int t = 0; t < KNB; t++) {
        d_cd[base0 + t] = bd0[t]; d_ci[base0 + t] = bi0[t];
        d_cd[base1 + t] = bd1[t]; d_ci[base1 + t] = bi1[t];
    }
}

// ---------------- KNN merge: 8 sorted 16-lists -> top 16 --------------------
__global__ void __launch_bounds__(256) knn_merge_kernel()
{
    int qi = blockIdx.x*256 + threadIdx.x;     // 0 .. 16383
    size_t base = (size_t)qi*128;
    float bd[KNB]; int bi[KNB];
    #pragma unroll
    for (int t = 0; t < KNB; t++) { bd[t] = 3.4e38f; bi[t] = 0; }
    for (int e = 0; e < 128; e++) {
        float d = d_cd[base + e];
        if (d < bd[KNB-1]) {
            int id = d_ci[base + e];
            KNN_INSERT(d, id, bd, bi);
        }
    }
    #pragma unroll
    for (int t = 0; t < KNB; t++) d_knn[(size_t)qi*KNB + t] = bi[t];
}

// ---------------- GEMM1: h1 = gather(feats) @ w1^T, + per-channel stats -----
// 256 threads, 128x128 tile, thread tile 8x8 (row-pair packed), occupancy 2.
#define G_LD 132
#define G1_SMEM ((LDF*G_LD*2)*4 + 128*4)
__global__ void __launch_bounds__(256,2) gemm1_kernel(const float* __restrict__ w1,
                                                      const float* __restrict__ p1)
{
    extern __shared__ float sm[];
    float* Asm = sm;                        // [68][132]  (k-major)
    float* Bsm = sm + LDF*G_LD;             // [68][132]
    int*   sj  = (int*)(Bsm + LDF*G_LD);    // 128 gathered point idx
    const int tid = threadIdx.x;
    const int r0 = blockIdx.x*128;
    const int b  = r0 >> 14;                // 16384 rows per batch

    if (tid < 128) {
        int r = r0 + tid;
        int j = d_knn[r];
        sj[tid] = j;
        int bm = r >> 4;
        size_t po = ((size_t)b*NN + j)*3;
        size_t qo = (size_t)bm*3;
        Asm[0*G_LD + tid] = p1[po+0] - d_p2[qo+0];
        Asm[1*G_LD + tid] = p1[po+1] - d_p2[qo+1];
        Asm[2*G_LD + tid] = p1[po+2] - d_p2[qo+2];
        Asm[3*G_LD + tid] = 0.f;
    }
    for (int f = tid; f < COUT*LDF; f += 256) {
        int o = f / LDF, c = f - o*LDF;
        float v;
        if (c < 3)       v = w1[o*67 + c];
        else if (c == 3) v = 0.f;
        else             v = w1[o*67 + (c-1)];
        Bsm[c*G_LD + o] = v;
    }
    __syncthreads();

    for (int f = tid; f < 128*16; f += 256) {
        int lr = f >> 4, c4 = f & 15;
        const float4 v = *(const float4*)(d_xt + ((size_t)b*NN + sj[lr])*CIN + c4*4);
        int c = 4 + c4*4;
        Asm[(c+0)*G_LD + lr] = v.x;
        Asm[(c+1)*G_LD + lr] = v.y;
        Asm[(c+2)*G_LD + lr] = v.z;
        Asm[(c+3)*G_LD + lr] = v.w;
    }
    __syncthreads();

    const int tx = tid & 15, ty = tid >> 4;      // tx 0..15 (col grp), ty 0..15 (row grp)
    const float* Ak = Asm + ty*8;
    const float* Bk = Bsm + tx*8;
    ull acc2[4][8];                              // [row-pair][col]
    #pragma unroll
    for (int i = 0; i < 4; i++)
        #pragma unroll
        for (int j = 0; j < 8; j++) acc2[i][j] = 0ull;

    for (int k = 0; k < LDF; k++) {
        ulonglong2 u0 = *(const ulonglong2*)(Ak + k*G_LD);      // rows 0-3
        ulonglong2 u1 = *(const ulonglong2*)(Ak + k*G_LD + 4);  // rows 4-7
        float4 q0 = *(const float4*)(Bk + k*G_LD);
        float4 q1 = *(const float4*)(Bk + k*G_LD + 4);
        ull bp[8];
        PACK2(bp[0], q0.x, q0.x); PACK2(bp[1], q0.y, q0.y);
        PACK2(bp[2], q0.z, q0.z); PACK2(bp[3], q0.w, q0.w);
        PACK2(bp[4], q1.x, q1.x); PACK2(bp[5], q1.y, q1.y);
        PACK2(bp[6], q1.z, q1.z); PACK2(bp[7], q1.w, q1.w);
        ull au[4] = {u0.x, u0.y, u1.x, u1.y};
        #pragma unroll
        for (int i = 0; i < 4; i++)
            #pragma unroll
            for (int j = 0; j < 8; j++) FMA2(acc2[i][j], au[i], bp[j]);
    }

    float acc[8][8];
    #pragma unroll
    for (int i = 0; i < 4; i++)
        #pragma unroll
        for (int j = 0; j < 8; j++)
            UNPACK2(acc[2*i][j], acc[2*i+1][j], acc2[i][j]);

    #pragma unroll
    for (int i = 0; i < 8; i++) {
        size_t row = (size_t)(r0 + ty*8 + i);
        *(float4*)&d_h1[row*COUT + tx*8]     = make_float4(acc[i][0],acc[i][1],acc[i][2],acc[i][3]);
        *(float4*)&d_h1[row*COUT + tx*8 + 4] = make_float4(acc[i][4],acc[i][5],acc[i][6],acc[i][7]);
    }

    __syncthreads();
    float* ssum = sm; float* ssq = sm + COUT;
    if (tid < COUT) { ssum[tid] = 0.f; ssq[tid] = 0.f; }
    __syncthreads();
    #pragma unroll
    for (int j = 0; j < 8; j++) {
        float s = 0.f, q = 0.f;
        #pragma unroll
        for (int i = 0; i < 8; i++) { float v = acc[i][j]; s += v; q += v*v; }
        atomicAdd(&ssum[tx*8 + j], s);
        atomicAdd(&ssq [tx*8 + j], q);
    }
    __syncthreads();
    if (tid < COUT) {
        atomicAdd(&d_s1[tid],        ssum[tid]);
        atomicAdd(&d_s1[COUT + tid], ssq[tid]);
    }
}

// ---------------- GEMM2: relu(bn1(h1)) @ w2^T -> stats + max over k ---------
// 256 threads, 128x128 tile, thread tile 8x8, K chunked 2x64, occupancy 2.
#define G2_SMEM ((64*G_LD*2 + 2*COUT)*4)
__global__ void __launch_bounds__(256,2) gemm2_kernel(const float* __restrict__ w2,
                                                      const float* __restrict__ g1,
                                                      const float* __restrict__ b1)
{
    extern __shared__ float sm[];
    float* Asm = sm;                        // [64][132] per chunk
    float* Bsm = sm + 64*G_LD;              // [64][132]
    float* alp = Bsm + 64*G_LD;
    float* bet = alp + COUT;
    const int tid = threadIdx.x;

    if (tid < COUT) {
        float mean = d_s1[tid] * (1.f/RR);
        float var  = d_s1[COUT+tid] * (1.f/RR) - mean*mean;
        float al = g1[tid] * rsqrtf(var + EPSV);
        alp[tid] = al;
        bet[tid] = b1[tid] - al*mean;
    }
    __syncthreads();

    const int r0 = blockIdx.x*128;
    const int tx = tid & 15, ty = tid >> 4;
    const float* Ak = Asm + ty*8;
    const float* Bk = Bsm + tx*8;
    ull acc2[4][8];
    #pragma unroll
    for (int i = 0; i < 4; i++)
        #pragma unroll
        for (int j = 0; j < 8; j++) acc2[i][j] = 0ull;

    for (int kc = 0; kc < 2; kc++) {
        if (kc) __syncthreads();                       // protect smem reuse
        // A chunk: relu(bn1(h1[r0..r0+127][kc*64 .. +63])) stored k-major
        for (int f = tid; f < 128*16; f += 256) {
            int lr = f >> 4, c4 = (f & 15)*4;
            int c = kc*64 + c4;
            float4 v = *(const float4*)&d_h1[(size_t)(r0+lr)*COUT + c];
            v.x = fmaxf(fmaf(alp[c+0], v.x, bet[c+0]), 0.f);
            v.y = fmaxf(fmaf(alp[c+1], v.y, bet[c+1]), 0.f);
            v.z = fmaxf(fmaf(alp[c+2], v.z, bet[c+2]), 0.f);
            v.w = fmaxf(fmaf(alp[c+3], v.w, bet[c+3]), 0.f);
            Asm[(c4+0)*G_LD + lr] = v.x;
            Asm[(c4+1)*G_LD + lr] = v.y;
            Asm[(c4+2)*G_LD + lr] = v.z;
            Asm[(c4+3)*G_LD + lr] = v.w;
        }
        // B chunk: w2[o][kc*64 .. +63] stored k-major
        for (int f = tid; f < 128*16; f += 256) {
            int o = f >> 4, c4 = (f & 15)*4;
            float4 w = *(const float4*)&w2[o*128 + kc*64 + c4];
            Bsm[(c4+0)*G_LD + o] = w.x;
            Bsm[(c4+1)*G_LD + o] = w.y;
            Bsm[(c4+2)*G_LD + o] = w.z;
            Bsm[(c4+3)*G_LD + o] = w.w;
        }
        __syncthreads();

        for (int k = 0; k < 64; k++) {
            ulonglong2 u0 = *(const ulonglong2*)(Ak + k*G_LD);
            ulonglong2 u1 = *(const ulonglong2*)(Ak + k*G_LD + 4);
            float4 q0 = *(const float4*)(Bk + k*G_LD);
            float4 q1 = *(const float4*)(Bk + k*G_LD + 4);
            ull bp[8];
            PACK2(bp[0], q0.x, q0.x); PACK2(bp[1], q0.y, q0.y);
            PACK2(bp[2], q0.z, q0.z); PACK2(bp[3], q0.w, q0.w);
            PACK2(bp[4], q1.x, q1.x); PACK2(bp[5], q1.y, q1.y);
            PACK2(bp[6], q1.z, q1.z); PACK2(bp[7], q1.w, q1.w);
            ull au[4] = {u0.x, u0.y, u1.x, u1.y};
            #pragma unroll
            for (int i = 0; i < 4; i++)
                #pragma unroll
                for (int j = 0; j < 8; j++) FMA2(acc2[i][j], au[i], bp[j]);
        }
    }

    float acc[8][8];
    #pragma unroll
    for (int i = 0; i < 4; i++)
        #pragma unroll
        for (int j = 0; j < 8; j++)
            UNPACK2(acc[2*i][j], acc[2*i+1][j], acc2[i][j]);

    // epilogue: per-(b,m) max + channel stats. No h2 store.
    __syncthreads();
    float* mxb  = sm;               // [8][128]
    float* ssum = sm + 1024;
    float* ssq  = ssum + COUT;
    if (tid < COUT) { ssum[tid] = 0.f; ssq[tid] = 0.f; }

    float vmax[8];
    #pragma unroll
    for (int j = 0; j < 8; j++) {
        float m = acc[0][j];
        #pragma unroll
        for (int i = 1; i < 8; i++) m = fmaxf(m, acc[i][j]);
        vmax[j] = m;
    }
    const int g = ty >> 1;                          // local bm group (0..7)
    if ((ty & 1) == 0) {
        #pragma unroll
        for (int j = 0; j < 8; j++) mxb[g*COUT + tx*8 + j] = vmax[j];
    }
    __syncthreads();
    if (ty & 1) {
        int bm = (r0 >> 4) + g;
        #pragma unroll
        for (int j = 0; j < 8; j++) {
            float m = fmaxf(mxb[g*COUT + tx*8 + j], vmax[j]);
            d_mx[(size_t)bm*COUT + tx*8 + j] = m;
        }
    }
    #pragma unroll
    for (int j = 0; j < 8; j++) {
        float s = 0.f, q = 0.f;
        #pragma unroll
        for (int i = 0; i < 8; i++) { float v = acc[i][j]; s += v; q += v*v; }
        atomicAdd(&ssum[tx*8 + j], s);
        atomicAdd(&ssq [tx*8 + j], q);
    }
    __syncthreads();
    if (tid < COUT) {
        atomicAdd(&d_s2[tid],        ssum[tid]);
        atomicAdd(&d_s2[COUT + tid], ssq[tid]);
    }
}

// ---------------- BN2 + ReLU on maxed values, transposed write --------------
__global__ void __launch_bounds__(COUT) final_kernel(const float* __restrict__ g2,
                                                     const float* __restrict__ b2,
                                                     float* __restrict__ outf)
{
    const int o = threadIdx.x;
    const int b = blockIdx.y, m0 = blockIdx.x*32;
    float mean = d_s2[o] * (1.f/RR);
    float var  = d_s2[COUT+o] * (1.f/RR) - mean*mean;
    float al = g2[o] * rsqrtf(var + EPSV);
    float be = b2[o] - al*mean;

    float ov[32];
    #pragma unroll
    for (int mm = 0; mm < 32; ++mm) {
        float v = d_mx[((size_t)(b*MM + m0 + mm))*COUT + o];
        ov[mm] = fmaxf(fmaf(al, v, be), 0.f);
    }
    float* orow = outf + ((size_t)b*COUT + o)*MM + m0;
    #pragma unroll
    for (int q = 0; q < 8; q++)
        ((float4*)orow)[q] = make_float4(ov[4*q], ov[4*q+1], ov[4*q+2], ov[4*q+3]);
}

// ---------------- launch ----------------------------------------------------
extern "C" void kernel_launch(void* const* d_in, const int* in_sizes, int n_in,
                              void* d_out, int out_size)
{
    const float* p1 = (const float*)d_in[0];
    const float* x1 = (const float*)d_in[1];
    const float* w1 = (const float*)d_in[2];
    const float* g1 = (const float*)d_in[3];
    const float* b1 = (const float*)d_in[4];
    const float* w2 = (const float*)d_in[5];
    const float* g2 = (const float*)d_in[6];
    const float* b2 = (const float*)d_in[7];
    float* out = (float*)d_out;

    cudaFuncSetAttribute(fps_tr_kernel,   cudaFuncAttributeMaxDynamicSharedMemorySize, FPS_SMEM);
    cudaFuncSetAttribute(knn_part_kernel, cudaFuncAttributeMaxDynamicSharedMemorySize, KNN_SMEM);
    cudaFuncSetAttribute(gemm1_kernel,    cudaFuncAttributeMaxDynamicSharedMemorySize, G1_SMEM);
    cudaFuncSetAttribute(gemm2_kernel,    cudaFuncAttributeMaxDynamicSharedMemorySize, G2_SMEM);

    fps_tr_kernel<<<BB + BB*2*128, 512, FPS_SMEM>>>(p1, x1, out);
    knn_part_kernel<<<dim3(16, BB), 256, KNN_SMEM>>>(p1);
    knn_merge_kernel<<<(BB*MM)/256, 256>>>();
    gemm1_kernel<<<RR/128, 256, G1_SMEM>>>(w1, p1);
    gemm2_kernel<<<RR/128, 256, G2_SMEM>>>(w2, g1, b1);
    final_kernel<<<dim3(MM/32, BB), COUT>>>(g2, b2, out + (size_t)BB*MM*3);
}

// round 15
// speedup vs baseline: 1.0270x; 1.0270x over previous
#include <cuda_runtime.h>
#include <cstdint>

#define BB   16
#define NN   4096
#define CIN  64
#define COUT 128
#define MM   1024
#define KNB  16
#define RR   (BB*MM*KNB)      // 262144 rows
#define LDF  68               // rel(3) + pad(1) + x(64)
#define EPSV 1e-5f
typedef unsigned long long ull;

// ---- packed f32x2 helpers --------------------------------------------------
#define PACK2(out, lo, hi)  asm("mov.b64 %0, {%1, %2};" : "=l"(out) : "f"(lo), "f"(hi))
#define UNPACK2(lo, hi, in) asm("mov.b64 {%0, %1}, %2;" : "=f"(lo), "=f"(hi) : "l"(in))
#define FMA2(acc, a, b)     asm("fma.rn.f32x2 %0, %1, %2, %3;" : "=l"(acc) : "l"(a), "l"(b), "l"(acc))
#define FMA2O(out, a, b, c) asm("fma.rn.f32x2 %0, %1, %2, %3;" : "=l"(out) : "l"(a), "l"(b), "l"(c))
#define ADD2(out, a, b)     asm("add.rn.f32x2 %0, %1, %2;" : "=l"(out) : "l"(a), "l"(b))
#define MUL2(out, a, b)     asm("mul.rn.f32x2 %0, %1, %2;" : "=l"(out) : "l"(a), "l"(b))

// ---------------- scratch (device globals; no allocation allowed) ----------
__device__ float d_xt[(size_t)BB*NN*CIN];        // 16 MB  x1 transposed [B,N,C]
__device__ float d_p2[(size_t)BB*MM*3];          // sampled centers
__device__ int   d_knn[(size_t)BB*MM*KNB];       // knn indices (global point idx)
__device__ float d_cd[(size_t)BB*MM*128];        // knn candidate dists (8 chunks x 16)
__device__ int   d_ci[(size_t)BB*MM*128];        // knn candidate idx
__device__ float d_h1[(size_t)RR*COUT];          // 134 MB
__device__ float d_mx[(size_t)BB*MM*COUT];       // 8 MB  per-(b,m) max of h2
__device__ float d_s1[2*COUT];                   // layer1 sum / sumsq
__device__ float d_s2[2*COUT];                   // layer2 sum / sumsq

// ---------------- FPS (blocks 0..15) + x1 transpose (blocks 16..) ----------
#define FPS_SMEM (192 + 3*NN*4 + MM*4)
__global__ void __launch_bounds__(512,1) fps_tr_kernel(const float* __restrict__ p1,
                                                       const float* __restrict__ x1,
                                                       float* __restrict__ out_p2)
{
    extern __shared__ char sraw[];
    const int tid = threadIdx.x;

    if (blockIdx.x >= BB) {
        // ---- transpose tile: [B,C,N] -> [B,N,C] ----
        float (*t)[33] = (float (*)[33])sraw;
        int tI = blockIdx.x - BB;
        if (tI == 0 && tid < 2*COUT) {        // fold stat zeroing in (runs before gemm1)
            d_s1[tid] = 0.f; d_s2[tid] = 0.f;
        }
        int b   = tI >> 8;
        int rem = tI & 255;
        int c0  = (rem >> 7) << 5;       // 0 or 32
        int n0  = (rem & 127) << 5;
        int tx = tid & 31, ty = tid >> 5;    // ty 0..15
        #pragma unroll
        for (int i = 0; i < 32; i += 16)
            t[ty+i][tx] = x1[((size_t)b*CIN + c0+ty+i)*NN + n0 + tx];
        __syncthreads();
        #pragma unroll
        for (int i = 0; i < 32; i += 16)
            d_xt[((size_t)b*NN + n0+ty+i)*CIN + c0 + tx] = t[tx][ty+i];
        return;
    }

    // ---- FPS: 512 threads, 8 points/thread (4 packed pairs) ----
    ull*   wkey = (ull*)sraw;                 // 16 per-warp keys
    float* px = (float*)(sraw + 192);
    float* py = px + NN;
    float* pz = py + NN;
    int*   sidx = (int*)(pz + NN);

    const int b = blockIdx.x;
    const int lane = tid & 31, wid = tid >> 5;
    const float* pb = p1 + (size_t)b*NN*3;

    for (int i = tid; i < NN; i += 512) {
        px[i] = pb[3*i+0]; py[i] = pb[3*i+1]; pz[i] = pb[3*i+2];
    }
    __syncthreads();

    ull rx2[4], ry2[4], rz2[4];
    float dist[8];
    #pragma unroll
    for (int pp = 0; pp < 4; pp++) {
        int j0 = tid + ((2*pp  ) << 9);
        int j1 = tid + ((2*pp+1) << 9);
        PACK2(rx2[pp], px[j0], px[j1]);
        PACK2(ry2[pp], py[j0], py[j1]);
        PACK2(rz2[pp], pz[j0], pz[j1]);
        dist[2*pp] = 1e10f; dist[2*pp+1] = 1e10f;
    }

    int far = 0;
    for (int it = 0; it < MM; ++it) {
        if (tid == 0) sidx[it] = far;
        float cx = px[far], cy = py[far], cz = pz[far];
        ull ncx2, ncy2, ncz2;
        { float nx = -cx, ny = -cy, nz = -cz;
          PACK2(ncx2, nx, nx); PACK2(ncy2, ny, ny); PACK2(ncz2, nz, nz); }

        #pragma unroll
        for (int pp = 0; pp < 4; pp++) {
            ull dx, dy, dz, dd;
            ADD2(dx, rx2[pp], ncx2);
            ADD2(dy, ry2[pp], ncy2);
            ADD2(dz, rz2[pp], ncz2);
            MUL2(dd, dz, dz);
            FMA2(dd, dy, dy);
            FMA2(dd, dx, dx);
            float d0, d1; UNPACK2(d0, d1, dd);
            dist[2*pp]   = fminf(dist[2*pp],   d0);
            dist[2*pp+1] = fminf(dist[2*pp+1], d1);
        }

        // per-thread argmax via u64 keys (d2 >= 0 so float order == uint order;
        // ~idx gives first-index tie-break). 3-level max tree, no serial chain.
        ull tk[8];
        #pragma unroll
        for (int q = 0; q < 8; q++)
            tk[q] = ((ull)__float_as_uint(dist[q]) << 32) | (unsigned)(~(tid + (q<<9)));
        ull k0 = tk[0] > tk[1] ? tk[0] : tk[1];
        ull k1 = tk[2] > tk[3] ? tk[2] : tk[3];
        ull k2 = tk[4] > tk[5] ? tk[4] : tk[5];
        ull k3 = tk[6] > tk[7] ? tk[6] : tk[7];
        ull k4 = k0 > k1 ? k0 : k1;
        ull k5 = k2 > k3 ? k2 : k3;
        ull kk = k4 > k5 ? k4 : k5;
        unsigned bku = (unsigned)(kk >> 32);
        unsigned bio = (unsigned)kk;              // = ~idx

        unsigned mk  = __reduce_max_sync(0xffffffffu, bku);
        unsigned cnd = (bku == mk) ? bio : 0u;    // max(~idx) == min idx
        unsigned mi  = __reduce_max_sync(0xffffffffu, cnd);
        if (lane == 0)
            wkey[wid] = ((ull)mk << 32) | mi;
        __syncthreads();

        // cross-warp: every warp reduces the 16 keys (4-level u64 shfl tree)
        ull k = wkey[lane & 15];
        #pragma unroll
        for (int off = 8; off > 0; off >>= 1) {
            ull o = __shfl_xor_sync(0xffffffffu, k, off);
            if (o > k) k = o;
        }
        far = (int)(~(unsigned)k);
    }
    __syncthreads();
    for (int m = tid; m < MM; m += 512) {
        int j = sidx[m];
        float x = px[j], y = py[j], z = pz[j];
        size_t o = ((size_t)b*MM + m)*3;
        d_p2[o+0] = x; d_p2[o+1] = y; d_p2[o+2] = z;
        out_p2[o+0] = x; out_p2[o+1] = y; out_p2[o+2] = z;
    }
}

// ---------------- KNN part: top-16 within a 512-point chunk, 2 queries/thr --
#define NCHK 512
#define KNN_SMEM (NCHK*32)

#define KNN_INSERT(d2v, idv, bd, bi)                                   \
    if ((d2v) < bd[KNB-1]) {                                           \
        bd[KNB-1] = (d2v); bi[KNB-1] = (idv);                          \
        _Pragma("unroll")                                              \
        for (int t = KNB-1; t > 0; --t) {                              \
            if (bd[t] < bd[t-1]) {                                     \
                float td = bd[t]; bd[t] = bd[t-1]; bd[t-1] = td;       \
                int   ti = bi[t]; bi[t] = bi[t-1]; bi[t-1] = ti;       \
            }                                                          \
        }                                                              \
    }

__global__ void __launch_bounds__(256) knn_part_kernel(const float* __restrict__ p1)
{
    extern __shared__ ull pn2[];           // [NCHK][4] : (xx, yy, zz, ww)
    const int b = blockIdx.y, tid = threadIdx.x;
    const int ch = blockIdx.x & 7;            // point chunk (0..7)
    const int qg = blockIdx.x >> 3;           // query group (0..1)
    const float* pb = p1 + (size_t)b*NN*3;

    for (int i = tid; i < NCHK; i += 256) {
        int g = ch*NCHK + i;
        float x = pb[3*g], y = pb[3*g+1], z = pb[3*g+2];
        float n1 = (x*x + y*y) + z*z;
        if (x == 0.f && y == 0.f && z == 0.f) n1 = __int_as_float(0x7f800000);
        ull xx, yy, zz, ww;
        PACK2(xx, x, x); PACK2(yy, y, y); PACK2(zz, z, z); PACK2(ww, n1, n1);
        pn2[i*4+0] = xx; pn2[i*4+1] = yy; pn2[i*4+2] = zz; pn2[i*4+3] = ww;
    }
    __syncthreads();

    const int m0 = qg*512 + tid;
    const int m1 = m0 + 256;
    size_t q0o = ((size_t)b*MM + m0)*3;
    size_t q1o = ((size_t)b*MM + m1)*3;
    float q0x = d_p2[q0o], q0y = d_p2[q0o+1], q0z = d_p2[q0o+2];
    float q1x = d_p2[q1o], q1y = d_p2[q1o+1], q1z = d_p2[q1o+2];
    float n20 = (q0x*q0x + q0y*q0y) + q0z*q0z;
    float n21 = (q1x*q1x + q1y*q1y) + q1z*q1z;

    ull qx01, qy01, qz01, n201, m2d;
    PACK2(qx01, q0x, q1x); PACK2(qy01, q0y, q1y); PACK2(qz01, q0z, q1z);
    PACK2(n201, n20, n21);
    { float m2 = -2.f; PACK2(m2d, m2, m2); }

    float bd0[KNB], bd1[KNB]; int bi0[KNB], bi1[KNB];
    #pragma unroll
    for (int t = 0; t < KNB; t++) {
        bd0[t] = 3.4e38f; bi0[t] = 0;
        bd1[t] = 3.4e38f; bi1[t] = 0;
    }

    #pragma unroll 4
    for (int j = 0; j < NCHK; j++) {
        const ulonglong2* pj = (const ulonglong2*)&pn2[j*4];
        ulonglong2 a = pj[0];                 // (xx, yy)
        ulonglong2 c = pj[1];                 // (zz, ww)
        int id = ch*NCHK + j;
        ull dot, t01, d01;
        MUL2(dot, qx01, a.x);
        FMA2(dot, qy01, a.y);
        FMA2(dot, qz01, c.x);
        ADD2(t01, n201, c.y);                 // n2 + n1
        FMA2O(d01, m2d, dot, t01);            // d2 = n2+n1 - 2 dot
        float d20, d21; UNPACK2(d20, d21, d01);
        KNN_INSERT(d20, id, bd0, bi0);
        KNN_INSERT(d21, id, bd1, bi1);
    }
    size_t base0 = ((size_t)b*MM + m0)*128 + ch*16;
    size_t base1 = ((size_t)b*MM + m1)*128 + ch*16;
    #pragma unroll
    for (int t = 0; t < KNB; t++) {
        d_cd[base0 + t] = bd0[t]; d_ci[base0 + t] = bi0[t];
        d_cd[base1 + t] = bd1[t]; d_ci[base1 + t] = bi1[t];
    }
}

// ---------------- KNN merge: 8 sorted 16-lists -> top 16 --------------------
__global__ void __launch_bounds__(256) knn_merge_kernel()
{
    int qi = blockIdx.x*256 + threadIdx.x;     // 0 .. 16383
    size_t base = (size_t)qi*128;
    float bd[KNB]; int bi[KNB];
    #pragma unroll
    for (int t = 0; t < KNB; t++) { bd[t] = 3.4e38f; bi[t] = 0; }
    for (int e = 0; e < 128; e++) {
        float d = d_cd[base + e];
        if (d < bd[KNB-1]) {
            int id = d_ci[base + e];
            KNN_INSERT(d, id, bd, bi);
        }
    }
    #pragma unroll
    for (int t = 0; t < KNB; t++) d_knn[(size_t)qi*KNB + t] = bi[t];
}

// ---------------- GEMM1: h1 = gather(feats) @ w1^T, + per-channel stats -----
// 512 threads, 128x128 tile, occupancy 2. Thread tile 8 rows x 4 cols with
// row-PAIR packed accumulators (A pairs come straight from k-major smem).
#define G_LD 132
#define G1_SMEM ((LDF*G_LD*2)*4 + 128*4)
__global__ void __launch_bounds__(512,2) gemm1_kernel(const float* __restrict__ w1,
                                                      const float* __restrict__ p1)
{
    extern __shared__ float sm[];
    float* Asm = sm;                        // [68][132]  (k-major)
    float* Bsm = sm + LDF*G_LD;             // [68][132]
    int*   sj  = (int*)(Bsm + LDF*G_LD);    // 128 gathered point idx
    const int tid = threadIdx.x;
    const int r0 = blockIdx.x*128;
    const int b  = r0 >> 14;                // 16384 rows per batch

    if (tid < 128) {
        int r = r0 + tid;
        int j = d_knn[r];
        sj[tid] = j;
        int bm = r >> 4;
        size_t po = ((size_t)b*NN + j)*3;
        size_t qo = (size_t)bm*3;
        Asm[0*G_LD + tid] = p1[po+0] - d_p2[qo+0];
        Asm[1*G_LD + tid] = p1[po+1] - d_p2[qo+1];
        Asm[2*G_LD + tid] = p1[po+2] - d_p2[qo+2];
        Asm[3*G_LD + tid] = 0.f;
    }
    for (int f = tid; f < COUT*LDF; f += 512) {
        int o = f / LDF, c = f - o*LDF;
        float v;
        if (c < 3)       v = w1[o*67 + c];
        else if (c == 3) v = 0.f;
        else             v = w1[o*67 + (c-1)];
        Bsm[c*G_LD + o] = v;
    }
    __syncthreads();

    for (int f = tid; f < 128*16; f += 512) {
        int lr = f >> 4, c4 = f & 15;
        const float4 v = *(const float4*)(d_xt + ((size_t)b*NN + sj[lr])*CIN + c4*4);
        int c = 4 + c4*4;
        Asm[(c+0)*G_LD + lr] = v.x;
        Asm[(c+1)*G_LD + lr] = v.y;
        Asm[(c+2)*G_LD + lr] = v.z;
        Asm[(c+3)*G_LD + lr] = v.w;
    }
    __syncthreads();

    const int tx = tid & 31, ty = tid >> 5;      // tx 0..31 (cols), ty 0..15 (rows)
    const float* Ak = Asm + ty*8;
    const float* Bk = Bsm + tx*4;
    ull acc2[4][4];                              // [row-pair][col]
    #pragma unroll
    for (int i = 0; i < 4; i++)
        #pragma unroll
        for (int j = 0; j < 4; j++) acc2[i][j] = 0ull;

    for (int k = 0; k < LDF; k++) {
        ulonglong2 u0 = *(const ulonglong2*)(Ak + k*G_LD);      // rows 0-3 (2 pairs)
        ulonglong2 u1 = *(const ulonglong2*)(Ak + k*G_LD + 4);  // rows 4-7
        float4 q = *(const float4*)(Bk + k*G_LD);
        ull bp[4];
        PACK2(bp[0], q.x, q.x); PACK2(bp[1], q.y, q.y);
        PACK2(bp[2], q.z, q.z); PACK2(bp[3], q.w, q.w);
        ull au[4] = {u0.x, u0.y, u1.x, u1.y};
        #pragma unroll
        for (int i = 0; i < 4; i++)
            #pragma unroll
            for (int j = 0; j < 4; j++) FMA2(acc2[i][j], au[i], bp[j]);
    }

    float acc[8][4];
    #pragma unroll
    for (int i = 0; i < 4; i++)
        #pragma unroll
        for (int j = 0; j < 4; j++)
            UNPACK2(acc[2*i][j], acc[2*i+1][j], acc2[i][j]);

    #pragma unroll
    for (int i = 0; i < 8; i++) {
        size_t row = (size_t)(r0 + ty*8 + i);
        *(float4*)&d_h1[row*COUT + tx*4] = make_float4(acc[i][0],acc[i][1],acc[i][2],acc[i][3]);
    }

    __syncthreads();
    float* ssum = sm; float* ssq = sm + COUT;
    if (tid < COUT) { ssum[tid] = 0.f; ssq[tid] = 0.f; }
    __syncthreads();
    #pragma unroll
    for (int j = 0; j < 4; j++) {
        float s = 0.f, q = 0.f;
        #pragma unroll
        for (int i = 0; i < 8; i++) { float v = acc[i][j]; s += v; q += v*v; }
        atomicAdd(&ssum[tx*4 + j], s);
        atomicAdd(&ssq [tx*4 + j], q);
    }
    __syncthreads();
    if (tid < COUT) {
        atomicAdd(&d_s1[tid],        ssum[tid]);
        atomicAdd(&d_s1[COUT + tid], ssq[tid]);
    }
}

// ---------------- GEMM2: relu(bn1(h1)) @ w2^T -> stats + max over k ---------
// 512 threads, 128x128 tile, K chunked 2x64, occupancy 2.
#define G2_SMEM ((64*G_LD*2 + 2*COUT)*4)
__global__ void __launch_bounds__(512,2) gemm2_kernel(const float* __restrict__ w2,
                                                      const float* __restrict__ g1,
                                                      const float* __restrict__ b1)
{
    extern __shared__ float sm[];
    float* Asm = sm;                        // [64][132] per chunk
    float* Bsm = sm + 64*G_LD;              // [64][132]
    float* alp = Bsm + 64*G_LD;
    float* bet = alp + COUT;
    const int tid = threadIdx.x;

    if (tid < COUT) {
        float mean = d_s1[tid] * (1.f/RR);
        float var  = d_s1[COUT+tid] * (1.f/RR) - mean*mean;
        float al = g1[tid] * rsqrtf(var + EPSV);
        alp[tid] = al;
        bet[tid] = b1[tid] - al*mean;
    }
    __syncthreads();

    const int r0 = blockIdx.x*128;
    const int tx = tid & 31, ty = tid >> 5;
    const float* Ak = Asm + ty*8;
    const float* Bk = Bsm + tx*4;
    ull acc2[4][4];
    #pragma unroll
    for (int i = 0; i < 4; i++)
        #pragma unroll
        for (int j = 0; j < 4; j++) acc2[i][j] = 0ull;

    for (int kc = 0; kc < 2; kc++) {
        if (kc) __syncthreads();                       // protect smem reuse
        // A chunk: relu(bn1(h1[r0..r0+127][kc*64 .. +63])) stored k-major
        for (int f = tid; f < 128*16; f += 512) {
            int lr = f >> 4, c4 = (f & 15)*4;
            int c = kc*64 + c4;
            float4 v = *(const float4*)&d_h1[(size_t)(r0+lr)*COUT + c];
            v.x = fmaxf(fmaf(alp[c+0], v.x, bet[c+0]), 0.f);
            v.y = fmaxf(fmaf(alp[c+1], v.y, bet[c+1]), 0.f);
            v.z = fmaxf(fmaf(alp[c+2], v.z, bet[c+2]), 0.f);
            v.w = fmaxf(fmaf(alp[c+3], v.w, bet[c+3]), 0.f);
            Asm[(c4+0)*G_LD + lr] = v.x;
            Asm[(c4+1)*G_LD + lr] = v.y;
            Asm[(c4+2)*G_LD + lr] = v.z;
            Asm[(c4+3)*G_LD + lr] = v.w;
        }
        // B chunk: w2[o][kc*64 .. +63] stored k-major
        for (int f = tid; f < 128*16; f += 512) {
            int o = f >> 4, c4 = (f & 15)*4;
            float4 w = *(const float4*)&w2[o*128 + kc*64 + c4];
            Bsm[(c4+0)*G_LD + o] = w.x;
            Bsm[(c4+1)*G_LD + o] = w.y;
            Bsm[(c4+2)*G_LD + o] = w.z;
            Bsm[(c4+3)*G_LD + o] = w.w;
        }
        __syncthreads();

        for (int k = 0; k < 64; k++) {
            ulonglong2 u0 = *(const ulonglong2*)(Ak + k*G_LD);
            ulonglong2 u1 = *(const ulonglong2*)(Ak + k*G_LD + 4);
            float4 q = *(const float4*)(Bk + k*G_LD);
            ull bp[4];
            PACK2(bp[0], q.x, q.x); PACK2(bp[1], q.y, q.y);
            PACK2(bp[2], q.z, q.z); PACK2(bp[3], q.w, q.w);
            ull au[4] = {u0.x, u0.y, u1.x, u1.y};
            #pragma unroll
            for (int i = 0; i < 4; i++)
                #pragma unroll
                for (int j = 0; j < 4; j++) FMA2(acc2[i][j], au[i], bp[j]);
        }
    }

    float acc[8][4];
    #pragma unroll
    for (int i = 0; i < 4; i++)
        #pragma unroll
        for (int j = 0; j < 4; j++)
            UNPACK2(acc[2*i][j], acc[2*i+1][j], acc2[i][j]);

    // epilogue: per-(b,m) max + channel stats. No h2 store.
    __syncthreads();
    float* mxb  = sm;               // [8][128]
    float* ssum = sm + 1024;
    float* ssq  = ssum + COUT;
    if (tid < COUT) { ssum[tid] = 0.f; ssq[tid] = 0.f; }

    float vmax[4];
    #pragma unroll
    for (int j = 0; j < 4; j++) {
        float m = acc[0][j];
        #pragma unroll
        for (int i = 1; i < 8; i++) m = fmaxf(m, acc[i][j]);
        vmax[j] = m;
    }
    const int g = ty >> 1;                          // local bm group (0..7)
    if ((ty & 1) == 0) {
        #pragma unroll
        for (int j = 0; j < 4; j++) mxb[g*COUT + tx*4 + j] = vmax[j];
    }
    __syncthreads();
    if (ty & 1) {
        int bm = (r0 >> 4) + g;
        #pragma unroll
        for (int j = 0; j < 4; j++) {
            float m = fmaxf(mxb[g*COUT + tx*4 + j], vmax[j]);
            d_mx[(size_t)bm*COUT + tx*4 + j] = m;
        }
    }
    #pragma unroll
    for (int j = 0; j < 4; j++) {
        float s = 0.f, q = 0.f;
        #pragma unroll
        for (int i = 0; i < 8; i++) { float v = acc[i][j]; s += v; q += v*v; }
        atomicAdd(&ssum[tx*4 + j], s);
        atomicAdd(&ssq [tx*4 + j], q);
    }
    __syncthreads();
    if (tid < COUT) {
        atomicAdd(&d_s2[tid],        ssum[tid]);
        atomicAdd(&d_s2[COUT + tid], ssq[tid]);
    }
}

// ---------------- BN2 + ReLU on maxed values, transposed write --------------
__global__ void __launch_bounds__(COUT) final_kernel(const float* __restrict__ g2,
                                                     const float* __restrict__ b2,
                                                     float* __restrict__ outf)
{
    const int o = threadIdx.x;
    const int b = blockIdx.y, m0 = blockIdx.x*32;
    float mean = d_s2[o] * (1.f/RR);
    float var  = d_s2[COUT+o] * (1.f/RR) - mean*mean;
    float al = g2[o] * rsqrtf(var + EPSV);
    float be = b2[o] - al*mean;

    float ov[32];
    #pragma unroll
    for (int mm = 0; mm < 32; ++mm) {
        float v = d_mx[((size_t)(b*MM + m0 + mm))*COUT + o];
        ov[mm] = fmaxf(fmaf(al, v, be), 0.f);
    }
    float* orow = outf + ((size_t)b*COUT + o)*MM + m0;
    #pragma unroll
    for (int q = 0; q < 8; q++)
        ((float4*)orow)[q] = make_float4(ov[4*q], ov[4*q+1], ov[4*q+2], ov[4*q+3]);
}

// ---------------- launch ----------------------------------------------------
extern "C" void kernel_launch(void* const* d_in, const int* in_sizes, int n_in,
                              void* d_out, int out_size)
{
    const float* p1 = (const float*)d_in[0];
    const float* x1 = (const float*)d_in[1];
    const float* w1 = (const float*)d_in[2];
    const float* g1 = (const float*)d_in[3];
    const float* b1 = (const float*)d_in[4];
    const float* w2 = (const float*)d_in[5];
    const float* g2 = (const float*)d_in[6];
    const float* b2 = (const float*)d_in[7];
    float* out = (float*)d_out;

    cudaFuncSetAttribute(fps_tr_kernel,   cudaFuncAttributeMaxDynamicSharedMemorySize, FPS_SMEM);
    cudaFuncSetAttribute(knn_part_kernel, cudaFuncAttributeMaxDynamicSharedMemorySize, KNN_SMEM);
    cudaFuncSetAttribute(gemm1_kernel,    cudaFuncAttributeMaxDynamicSharedMemorySize, G1_SMEM);
    cudaFuncSetAttribute(gemm2_kernel,    cudaFuncAttributeMaxDynamicSharedMemorySize, G2_SMEM);

    fps_tr_kernel<<<BB + BB*2*128, 512, FPS_SMEM>>>(p1, x1, out);
    knn_part_kernel<<<dim3(16, BB), 256, KNN_SMEM>>>(p1);
    knn_merge_kernel<<<(BB*MM)/256, 256>>>();
    gemm1_kernel<<<RR/128, 512, G1_SMEM>>>(w1, p1);
    gemm2_kernel<<<RR/128, 512, G2_SMEM>>>(w2, g1, b1);
    final_kernel<<<dim3(MM/32, BB), COUT>>>(g2, b2, out + (size_t)BB*MM*3);
}

// round 16
// speedup vs baseline: 1.0562x; 1.0285x over previous
#include <cuda_runtime.h>
#include <cstdint>

#define BB   16
#define NN   4096
#define CIN  64
#define COUT 128
#define MM   1024
#define KNB  16
#define RR   (BB*MM*KNB)      // 262144 rows
#define LDF  68               // rel(3) + pad(1) + x(64)
#define EPSV 1e-5f
typedef unsigned long long ull;

// ---- packed f32x2 helpers --------------------------------------------------
#define PACK2(out, lo, hi)  asm("mov.b64 %0, {%1, %2};" : "=l"(out) : "f"(lo), "f"(hi))
#define UNPACK2(lo, hi, in) asm("mov.b64 {%0, %1}, %2;" : "=f"(lo), "=f"(hi) : "l"(in))
#define FMA2(acc, a, b)     asm("fma.rn.f32x2 %0, %1, %2, %3;" : "=l"(acc) : "l"(a), "l"(b), "l"(acc))
#define FMA2O(out, a, b, c) asm("fma.rn.f32x2 %0, %1, %2, %3;" : "=l"(out) : "l"(a), "l"(b), "l"(c))
#define ADD2(out, a, b)     asm("add.rn.f32x2 %0, %1, %2;" : "=l"(out) : "l"(a), "l"(b))
#define MUL2(out, a, b)     asm("mul.rn.f32x2 %0, %1, %2;" : "=l"(out) : "l"(a), "l"(b))

// ---------------- scratch (device globals; no allocation allowed) ----------
__device__ float d_xt[(size_t)BB*NN*CIN];        // 16 MB  x1 transposed [B,N,C]
__device__ float d_p2[(size_t)BB*MM*3];          // sampled centers
__device__ int   d_knn[(size_t)BB*MM*KNB];       // knn indices (global point idx)
__device__ float d_cd[(size_t)BB*MM*128];        // knn candidate dists (8 chunks x 16)
__device__ int   d_ci[(size_t)BB*MM*128];        // knn candidate idx
__device__ float d_h1[(size_t)RR*COUT];          // 134 MB
__device__ float d_mx[(size_t)BB*MM*COUT];       // 8 MB  per-(b,m) max of h2
__device__ float d_s1[2*COUT];                   // layer1 sum / sumsq
__device__ float d_s2[2*COUT];                   // layer2 sum / sumsq

// ---------------- FPS (blocks 0..15) + x1 transpose (blocks 16..) ----------
#define FPS_SMEM (192 + 3*NN*4 + MM*4)
__global__ void __launch_bounds__(512,1) fps_tr_kernel(const float* __restrict__ p1,
                                                       const float* __restrict__ x1,
                                                       float* __restrict__ out_p2)
{
    extern __shared__ char sraw[];
    const int tid = threadIdx.x;

    if (blockIdx.x >= BB) {
        // ---- transpose tile: [B,C,N] -> [B,N,C] ----
        float (*t)[33] = (float (*)[33])sraw;
        int tI = blockIdx.x - BB;
        if (tI == 0 && tid < 2*COUT) {        // fold stat zeroing in (runs before gemm1)
            d_s1[tid] = 0.f; d_s2[tid] = 0.f;
        }
        int b   = tI >> 8;
        int rem = tI & 255;
        int c0  = (rem >> 7) << 5;       // 0 or 32
        int n0  = (rem & 127) << 5;
        int tx = tid & 31, ty = tid >> 5;    // ty 0..15
        #pragma unroll
        for (int i = 0; i < 32; i += 16)
            t[ty+i][tx] = x1[((size_t)b*CIN + c0+ty+i)*NN + n0 + tx];
        __syncthreads();
        #pragma unroll
        for (int i = 0; i < 32; i += 16)
            d_xt[((size_t)b*NN + n0+ty+i)*CIN + c0 + tx] = t[tx][ty+i];
        return;
    }

    // ---- FPS: 512 threads, 8 points/thread (4 packed pairs) ----
    ull*   wkey = (ull*)sraw;                 // 16 per-warp keys
    float* px = (float*)(sraw + 192);
    float* py = px + NN;
    float* pz = py + NN;
    int*   sidx = (int*)(pz + NN);

    const int b = blockIdx.x;
    const int lane = tid & 31, wid = tid >> 5;
    const float* pb = p1 + (size_t)b*NN*3;

    for (int i = tid; i < NN; i += 512) {
        px[i] = pb[3*i+0]; py[i] = pb[3*i+1]; pz[i] = pb[3*i+2];
    }
    __syncthreads();

    ull rx2[4], ry2[4], rz2[4];
    float dist[8];
    #pragma unroll
    for (int pp = 0; pp < 4; pp++) {
        int j0 = tid + ((2*pp  ) << 9);
        int j1 = tid + ((2*pp+1) << 9);
        PACK2(rx2[pp], px[j0], px[j1]);
        PACK2(ry2[pp], py[j0], py[j1]);
        PACK2(rz2[pp], pz[j0], pz[j1]);
        dist[2*pp] = 1e10f; dist[2*pp+1] = 1e10f;
    }

    int far = 0;
    for (int it = 0; it < MM; ++it) {
        if (tid == 0) sidx[it] = far;
        float cx = px[far], cy = py[far], cz = pz[far];
        ull ncx2, ncy2, ncz2;
        { float nx = -cx, ny = -cy, nz = -cz;
          PACK2(ncx2, nx, nx); PACK2(ncy2, ny, ny); PACK2(ncz2, nz, nz); }

        #pragma unroll
        for (int pp = 0; pp < 4; pp++) {
            ull dx, dy, dz, dd;
            ADD2(dx, rx2[pp], ncx2);
            ADD2(dy, ry2[pp], ncy2);
            ADD2(dz, rz2[pp], ncz2);
            MUL2(dd, dz, dz);
            FMA2(dd, dy, dy);
            FMA2(dd, dx, dx);
            float d0, d1; UNPACK2(d0, d1, dd);
            dist[2*pp]   = fminf(dist[2*pp],   d0);
            dist[2*pp+1] = fminf(dist[2*pp+1], d1);
        }

        // per-thread argmax (first-index tie-break: earlier q wins)
        float bd = dist[0]; int bi = tid;
        #pragma unroll
        for (int q = 1; q < 8; q++)
            if (dist[q] > bd) { bd = dist[q]; bi = tid + (q<<9); }

        unsigned bku = __float_as_uint(bd);
        unsigned mk  = __reduce_max_sync(0xffffffffu, bku);
        unsigned cnd = (bku == mk) ? (unsigned)bi : 0xffffffffu;
        unsigned mi  = __reduce_min_sync(0xffffffffu, cnd);
        if (lane == 0)
            wkey[wid] = ((ull)mk << 32) | (unsigned)(~mi);
        __syncthreads();

        // cross-warp: every warp reduces the 16 keys (4-level u64 shfl tree)
        ull k = wkey[lane & 15];
        #pragma unroll
        for (int off = 8; off > 0; off >>= 1) {
            ull o = __shfl_xor_sync(0xffffffffu, k, off);
            if (o > k) k = o;
        }
        far = (int)(~(unsigned)k);
    }
    __syncthreads();
    for (int m = tid; m < MM; m += 512) {
        int j = sidx[m];
        float x = px[j], y = py[j], z = pz[j];
        size_t o = ((size_t)b*MM + m)*3;
        d_p2[o+0] = x; d_p2[o+1] = y; d_p2[o+2] = z;
        out_p2[o+0] = x; out_p2[o+1] = y; out_p2[o+2] = z;
    }
}

// ---------------- KNN part: top-16 within a 512-point chunk, 2 queries/thr --
#define NCHK 512
#define KNN_SMEM (NCHK*32)

#define KNN_INSERT(d2v, idv, bd, bi)                                   \
    if ((d2v) < bd[KNB-1]) {                                           \
        bd[KNB-1] = (d2v); bi[KNB-1] = (idv);                          \
        _Pragma("unroll")                                              \
        for (int t = KNB-1; t > 0; --t) {                              \
            if (bd[t] < bd[t-1]) {                                     \
                float td = bd[t]; bd[t] = bd[t-1]; bd[t-1] = td;       \
                int   ti = bi[t]; bi[t] = bi[t-1]; bi[t-1] = ti;       \
            }                                                          \
        }                                                              \
    }

__global__ void __launch_bounds__(256) knn_part_kernel(const float* __restrict__ p1)
{
    extern __shared__ ull pn2[];           // [NCHK][4] : (xx, yy, zz, ww)
    const int b = blockIdx.y, tid = threadIdx.x;
    const int ch = blockIdx.x & 7;            // point chunk (0..7)
    const int qg = blockIdx.x >> 3;           // query group (0..1)
    const float* pb = p1 + (size_t)b*NN*3;

    for (int i = tid; i < NCHK; i += 256) {
        int g = ch*NCHK + i;
        float x = pb[3*g], y = pb[3*g+1], z = pb[3*g+2];
        float n1 = (x*x + y*y) + z*z;
        if (x == 0.f && y == 0.f && z == 0.f) n1 = __int_as_float(0x7f800000);
        ull xx, yy, zz, ww;
        PACK2(xx, x, x); PACK2(yy, y, y); PACK2(zz, z, z); PACK2(ww, n1, n1);
        pn2[i*4+0] = xx; pn2[i*4+1] = yy; pn2[i*4+2] = zz; pn2[i*4+3] = ww;
    }
    __syncthreads();

    const int m0 = qg*512 + tid;
    const int m1 = m0 + 256;
    size_t q0o = ((size_t)b*MM + m0)*3;
    size_t q1o = ((size_t)b*MM + m1)*3;
    float q0x = d_p2[q0o], q0y = d_p2[q0o+1], q0z = d_p2[q0o+2];
    float q1x = d_p2[q1o], q1y = d_p2[q1o+1], q1z = d_p2[q1o+2];
    float n20 = (q0x*q0x + q0y*q0y) + q0z*q0z;
    float n21 = (q1x*q1x + q1y*q1y) + q1z*q1z;

    ull qx01, qy01, qz01, n201, m2d;
    PACK2(qx01, q0x, q1x); PACK2(qy01, q0y, q1y); PACK2(qz01, q0z, q1z);
    PACK2(n201, n20, n21);
    { float m2 = -2.f; PACK2(m2d, m2, m2); }

    float bd0[KNB], bd1[KNB]; int bi0[KNB], bi1[KNB];
    #pragma unroll
    for (int t = 0; t < KNB; t++) {
        bd0[t] = 3.4e38f; bi0[t] = 0;
        bd1[t] = 3.4e38f; bi1[t] = 0;
    }

    #pragma unroll 4
    for (int j = 0; j < NCHK; j++) {
        const ulonglong2* pj = (const ulonglong2*)&pn2[j*4];
        ulonglong2 a = pj[0];                 // (xx, yy)
        ulonglong2 c = pj[1];                 // (zz, ww)
        int id = ch*NCHK + j;
        ull dot, t01, d01;
        MUL2(dot, qx01, a.x);
        FMA2(dot, qy01, a.y);
        FMA2(dot, qz01, c.x);
        ADD2(t01, n201, c.y);                 // n2 + n1
        FMA2O(d01, m2d, dot, t01);            // d2 = n2+n1 - 2 dot
        float d20, d21; UNPACK2(d20, d21, d01);
        KNN_INSERT(d20, id, bd0, bi0);
        KNN_INSERT(d21, id, bd1, bi1);
    }
    size_t base0 = ((size_t)b*MM + m0)*128 + ch*16;
    size_t base1 = ((size_t)b*MM + m1)*128 + ch*16;
    #pragma unroll
    for (int t = 0; t < KNB; t++) {
        d_cd[base0 + t] = bd0[t]; d_ci[base0 + t] = bi0[t];
        d_cd[base1 + t] = bd1[t]; d_ci[base1 + t] = bi1[t];
    }
}

// ---------------- KNN merge: 8 sorted 16-lists -> top 16 --------------------
__global__ void __launch_bounds__(256) knn_merge_kernel()
{
    int qi = blockIdx.x*256 + threadIdx.x;     // 0 .. 16383
    size_t base = (size_t)qi*128;
    float bd[KNB]; int bi[KNB];
    #pragma unroll
    for (int t = 0; t < KNB; t++) { bd[t] = 3.4e38f; bi[t] = 0; }
    for (int e = 0; e < 128; e++) {
        float d = d_cd[base + e];
        if (d < bd[KNB-1]) {
            int id = d_ci[base + e];
            KNN_INSERT(d, id, bd, bi);
        }
    }
    #pragma unroll
    for (int t = 0; t < KNB; t++) d_knn[(size_t)qi*KNB + t] = bi[t];
}

// ---------------- GEMM1: h1 = gather(feats) @ w1^T, + per-channel stats -----
// 512 threads, 128x128 tile, occupancy 2. Thread tile 8 rows x 4 cols with
// row-PAIR packed accumulators (A pairs come straight from k-major smem).
#define G_LD 132
#define G1_SMEM ((LDF*G_LD*2)*4 + 128*4)
__global__ void __launch_bounds__(512,2) gemm1_kernel(const float* __restrict__ w1,
                                                      const float* __restrict__ p1)
{
    extern __shared__ float sm[];
    float* Asm = sm;                        // [68][132]  (k-major)
    float* Bsm = sm + LDF*G_LD;             // [68][132]
    int*   sj  = (int*)(Bsm + LDF*G_LD);    // 128 gathered point idx
    const int tid = threadIdx.x;
    const int r0 = blockIdx.x*128;
    const int b  = r0 >> 14;                // 16384 rows per batch

    if (tid < 128) {
        int r = r0 + tid;
        int j = d_knn[r];
        sj[tid] = j;
        int bm = r >> 4;
        size_t po = ((size_t)b*NN + j)*3;
        size_t qo = (size_t)bm*3;
        Asm[0*G_LD + tid] = p1[po+0] - d_p2[qo+0];
        Asm[1*G_LD + tid] = p1[po+1] - d_p2[qo+1];
        Asm[2*G_LD + tid] = p1[po+2] - d_p2[qo+2];
        Asm[3*G_LD + tid] = 0.f;
    }
    for (int f = tid; f < COUT*LDF; f += 512) {
        int o = f / LDF, c = f - o*LDF;
        float v;
        if (c < 3)       v = w1[o*67 + c];
        else if (c == 3) v = 0.f;
        else             v = w1[o*67 + (c-1)];
        Bsm[c*G_LD + o] = v;
    }
    __syncthreads();

    for (int f = tid; f < 128*16; f += 512) {
        int lr = f >> 4, c4 = f & 15;
        const float4 v = *(const float4*)(d_xt + ((size_t)b*NN + sj[lr])*CIN + c4*4);
        int c = 4 + c4*4;
        Asm[(c+0)*G_LD + lr] = v.x;
        Asm[(c+1)*G_LD + lr] = v.y;
        Asm[(c+2)*G_LD + lr] = v.z;
        Asm[(c+3)*G_LD + lr] = v.w;
    }
    __syncthreads();

    const int tx = tid & 31, ty = tid >> 5;      // tx 0..31 (cols), ty 0..15 (rows)
    const float* Ak = Asm + ty*8;
    const float* Bk = Bsm + tx*4;
    ull acc2[4][4];                              // [row-pair][col]
    #pragma unroll
    for (int i = 0; i < 4; i++)
        #pragma unroll
        for (int j = 0; j < 4; j++) acc2[i][j] = 0ull;

    for (int k = 0; k < LDF; k++) {
        ulonglong2 u0 = *(const ulonglong2*)(Ak + k*G_LD);      // rows 0-3 (2 pairs)
        ulonglong2 u1 = *(const ulonglong2*)(Ak + k*G_LD + 4);  // rows 4-7
        float4 q = *(const float4*)(Bk + k*G_LD);
        ull bp[4];
        PACK2(bp[0], q.x, q.x); PACK2(bp[1], q.y, q.y);
        PACK2(bp[2], q.z, q.z); PACK2(bp[3], q.w, q.w);
        ull au[4] = {u0.x, u0.y, u1.x, u1.y};
        #pragma unroll
        for (int i = 0; i < 4; i++)
            #pragma unroll
            for (int j = 0; j < 4; j++) FMA2(acc2[i][j], au[i], bp[j]);
    }

    float acc[8][4];
    #pragma unroll
    for (int i = 0; i < 4; i++)
        #pragma unroll
        for (int j = 0; j < 4; j++)
            UNPACK2(acc[2*i][j], acc[2*i+1][j], acc2[i][j]);

    #pragma unroll
    for (int i = 0; i < 8; i++) {
        size_t row = (size_t)(r0 + ty*8 + i);
        *(float4*)&d_h1[row*COUT + tx*4] = make_float4(acc[i][0],acc[i][1],acc[i][2],acc[i][3]);
    }

    __syncthreads();
    float* ssum = sm; float* ssq = sm + COUT;
    if (tid < COUT) { ssum[tid] = 0.f; ssq[tid] = 0.f; }
    __syncthreads();
    #pragma unroll
    for (int j = 0; j < 4; j++) {
        float s = 0.f, q = 0.f;
        #pragma unroll
        for (int i = 0; i < 8; i++) { float v = acc[i][j]; s += v; q += v*v; }
        atomicAdd(&ssum[tx*4 + j], s);
        atomicAdd(&ssq [tx*4 + j], q);
    }
    __syncthreads();
    if (tid < COUT) {
        atomicAdd(&d_s1[tid],        ssum[tid]);
        atomicAdd(&d_s1[COUT + tid], ssq[tid]);
    }
}

// ---------------- GEMM2: relu(bn1(h1)) @ w2^T -> stats + max over k ---------
// 512 threads, 128x128 tile, K chunked 2x64, full-B preload, occupancy 2.
#define G2_SMEM ((128*G_LD + 64*G_LD + 2*COUT)*4)
__global__ void __launch_bounds__(512,2) gemm2_kernel(const float* __restrict__ w2,
                                                      const float* __restrict__ g1,
                                                      const float* __restrict__ b1)
{
    extern __shared__ float sm[];
    float* Bsm = sm;                        // [128][132]  full B, k-major
    float* Asm = sm + 128*G_LD;             // [64][132]   A chunk, k-major
    float* alp = Asm + 64*G_LD;
    float* bet = alp + COUT;
    const int tid = threadIdx.x;

    if (tid < COUT) {
        float mean = d_s1[tid] * (1.f/RR);
        float var  = d_s1[COUT+tid] * (1.f/RR) - mean*mean;
        float al = g1[tid] * rsqrtf(var + EPSV);
        alp[tid] = al;
        bet[tid] = b1[tid] - al*mean;
    }
    // B full: w2[o][c] k-major (no sync needed against alp/bet: disjoint smem)
    for (int f = tid; f < 128*32; f += 512) {
        int o = f >> 5, c4 = (f & 31)*4;
        float4 w = *(const float4*)&w2[o*128 + c4];
        Bsm[(c4+0)*G_LD + o] = w.x;
        Bsm[(c4+1)*G_LD + o] = w.y;
        Bsm[(c4+2)*G_LD + o] = w.z;
        Bsm[(c4+3)*G_LD + o] = w.w;
    }
    __syncthreads();

    const int r0 = blockIdx.x*128;
    const int tx = tid & 31, ty = tid >> 5;
    const float* Ak = Asm + ty*8;
    const float* Bk = Bsm + tx*4;
    ull acc2[4][4];
    #pragma unroll
    for (int i = 0; i < 4; i++)
        #pragma unroll
        for (int j = 0; j < 4; j++) acc2[i][j] = 0ull;

    for (int kc = 0; kc < 2; kc++) {
        if (kc) __syncthreads();                       // protect A smem reuse
        // A chunk: relu(bn1(h1[r0..r0+127][kc*64 .. +63])) stored k-major
        for (int f = tid; f < 128*16; f += 512) {
            int lr = f >> 4, c4 = (f & 15)*4;
            int c = kc*64 + c4;
            float4 v = *(const float4*)&d_h1[(size_t)(r0+lr)*COUT + c];
            v.x = fmaxf(fmaf(alp[c+0], v.x, bet[c+0]), 0.f);
            v.y = fmaxf(fmaf(alp[c+1], v.y, bet[c+1]), 0.f);
            v.z = fmaxf(fmaf(alp[c+2], v.z, bet[c+2]), 0.f);
            v.w = fmaxf(fmaf(alp[c+3], v.w, bet[c+3]), 0.f);
            Asm[(c4+0)*G_LD + lr] = v.x;
            Asm[(c4+1)*G_LD + lr] = v.y;
            Asm[(c4+2)*G_LD + lr] = v.z;
            Asm[(c4+3)*G_LD + lr] = v.w;
        }
        __syncthreads();

        const float* Bkc = Bk + kc*64*G_LD;
        for (int k = 0; k < 64; k++) {
            ulonglong2 u0 = *(const ulonglong2*)(Ak + k*G_LD);
            ulonglong2 u1 = *(const ulonglong2*)(Ak + k*G_LD + 4);
            float4 q = *(const float4*)(Bkc + k*G_LD);
            ull bp[4];
            PACK2(bp[0], q.x, q.x); PACK2(bp[1], q.y, q.y);
            PACK2(bp[2], q.z, q.z); PACK2(bp[3], q.w, q.w);
            ull au[4] = {u0.x, u0.y, u1.x, u1.y};
            #pragma unroll
            for (int i = 0; i < 4; i++)
                #pragma unroll
                for (int j = 0; j < 4; j++) FMA2(acc2[i][j], au[i], bp[j]);
        }
    }

    float acc[8][4];
    #pragma unroll
    for (int i = 0; i < 4; i++)
        #pragma unroll
        for (int j = 0; j < 4; j++)
            UNPACK2(acc[2*i][j], acc[2*i+1][j], acc2[i][j]);

    // epilogue: per-(b,m) max + channel stats. No h2 store.
    __syncthreads();
    float* mxb  = sm;               // [8][128]
    float* ssum = sm + 1024;
    float* ssq  = ssum + COUT;
    if (tid < COUT) { ssum[tid] = 0.f; ssq[tid] = 0.f; }

    float vmax[4];
    #pragma unroll
    for (int j = 0; j < 4; j++) {
        float m = acc[0][j];
        #pragma unroll
        for (int i = 1; i < 8; i++) m = fmaxf(m, acc[i][j]);
        vmax[j] = m;
    }
    const int g = ty >> 1;                          // local bm group (0..7)
    if ((ty & 1) == 0) {
        #pragma unroll
        for (int j = 0; j < 4; j++) mxb[g*COUT + tx*4 + j] = vmax[j];
    }
    __syncthreads();
    if (ty & 1) {
        int bm = (r0 >> 4) + g;
        #pragma unroll
        for (int j = 0; j < 4; j++) {
            float m = fmaxf(mxb[g*COUT + tx*4 + j], vmax[j]);
            d_mx[(size_t)bm*COUT + tx*4 + j] = m;
        }
    }
    #pragma unroll
    for (int j = 0; j < 4; j++) {
        float s = 0.f, q = 0.f;
        #pragma unroll
        for (int i = 0; i < 8; i++) { float v = acc[i][j]; s += v; q += v*v; }
        atomicAdd(&ssum[tx*4 + j], s);
        atomicAdd(&ssq [tx*4 + j], q);
    }
    __syncthreads();
    if (tid < COUT) {
        atomicAdd(&d_s2[tid],        ssum[tid]);
        atomicAdd(&d_s2[COUT + tid], ssq[tid]);
    }
}

// ---------------- BN2 + ReLU on maxed values, transposed write --------------
__global__ void __launch_bounds__(COUT) final_kernel(const float* __restrict__ g2,
                                                     const float* __restrict__ b2,
                                                     float* __restrict__ outf)
{
    const int o = threadIdx.x;
    const int b = blockIdx.y, m0 = blockIdx.x*32;
    float mean = d_s2[o] * (1.f/RR);
    float var  = d_s2[COUT+o] * (1.f/RR) - mean*mean;
    float al = g2[o] * rsqrtf(var + EPSV);
    float be = b2[o] - al*mean;

    float ov[32];
    #pragma unroll
    for (int mm = 0; mm < 32; ++mm) {
        float v = d_mx[((size_t)(b*MM + m0 + mm))*COUT + o];
        ov[mm] = fmaxf(fmaf(al, v, be), 0.f);
    }
    float* orow = outf + ((size_t)b*COUT + o)*MM + m0;
    #pragma unroll
    for (int q = 0; q < 8; q++)
        ((float4*)orow)[q] = make_float4(ov[4*q], ov[4*q+1], ov[4*q+2], ov[4*q+3]);
}

// ---------------- launch ----------------------------------------------------
extern "C" void kernel_launch(void* const* d_in, const int* in_sizes, int n_in,
                              void* d_out, int out_size)
{
    const float* p1 = (const float*)d_in[0];
    const float* x1 = (const float*)d_in[1];
    const float* w1 = (const float*)d_in[2];
    const float* g1 = (const float*)d_in[3];
    const float* b1 = (const float*)d_in[4];
    const float* w2 = (const float*)d_in[5];
    const float* g2 = (const float*)d_in[6];
    const float* b2 = (const float*)d_in[7];
    float* out = (float*)d_out;

    cudaFuncSetAttribute(fps_tr_kernel,   cudaFuncAttributeMaxDynamicSharedMemorySize, FPS_SMEM);
    cudaFuncSetAttribute(knn_part_kernel, cudaFuncAttributeMaxDynamicSharedMemorySize, KNN_SMEM);
    cudaFuncSetAttribute(gemm1_kernel,    cudaFuncAttributeMaxDynamicSharedMemorySize, G1_SMEM);
    cudaFuncSetAttribute(gemm2_kernel,    cudaFuncAttributeMaxDynamicSharedMemorySize, G2_SMEM);

    fps_tr_kernel<<<BB + BB*2*128, 512, FPS_SMEM>>>(p1, x1, out);
    knn_part_kernel<<<dim3(16, BB), 256, KNN_SMEM>>>(p1);
    knn_merge_kernel<<<(BB*MM)/256, 256>>>();
    gemm1_kernel<<<RR/128, 512, G1_SMEM>>>(w1, p1);
    gemm2_kernel<<<RR/128, 512, G2_SMEM>>>(w2, g1, b1);
    final_kernel<<<dim3(MM/32, BB), COUT>>>(g2, b2, out + (size_t)BB*MM*3);
}

// round 17
// speedup vs baseline: 1.1183x; 1.0588x over previous
#include <cuda_runtime.h>
#include <cstdint>

#define BB   16
#define NN   4096
#define CIN  64
#define COUT 128
#define MM   1024
#define KNB  16
#define RR   (BB*MM*KNB)      // 262144 rows
#define LDF  68               // rel(3) + pad(1) + x(64)
#define EPSV 1e-5f
typedef unsigned long long ull;

// ---- packed f32x2 helpers --------------------------------------------------
#define PACK2(out, lo, hi)  asm("mov.b64 %0, {%1, %2};" : "=l"(out) : "f"(lo), "f"(hi))
#define UNPACK2(lo, hi, in) asm("mov.b64 {%0, %1}, %2;" : "=f"(lo), "=f"(hi) : "l"(in))
#define FMA2(acc, a, b)     asm("fma.rn.f32x2 %0, %1, %2, %3;" : "=l"(acc) : "l"(a), "l"(b), "l"(acc))
#define FMA2O(out, a, b, c) asm("fma.rn.f32x2 %0, %1, %2, %3;" : "=l"(out) : "l"(a), "l"(b), "l"(c))
#define ADD2(out, a, b)     asm("add.rn.f32x2 %0, %1, %2;" : "=l"(out) : "l"(a), "l"(b))
#define MUL2(out, a, b)     asm("mul.rn.f32x2 %0, %1, %2;" : "=l"(out) : "l"(a), "l"(b))

// ---------------- scratch (device globals; no allocation allowed) ----------
__device__ float d_xt[(size_t)BB*NN*CIN];        // 16 MB  x1 transposed [B,N,C]
__device__ float d_p2[(size_t)BB*MM*3];          // sampled centers
__device__ int   d_knn[(size_t)BB*MM*KNB];       // knn indices (global point idx)
__device__ float d_cd[(size_t)BB*MM*128];        // knn candidate dists (8 chunks x 16)
__device__ int   d_ci[(size_t)BB*MM*128];        // knn candidate idx
__device__ float d_h1[(size_t)RR*COUT];          // 134 MB
__device__ float d_mx[(size_t)BB*MM*COUT];       // 8 MB  per-(b,m) max of h2
__device__ float d_s1[2*COUT];                   // layer1 sum / sumsq
__device__ float d_s2[2*COUT];                   // layer2 sum / sumsq

// ---------------- FPS (blocks 0..15) + x1 transpose (blocks 16..) ----------
#define FPS_SMEM (192 + 3*NN*4 + MM*4)
__global__ void __launch_bounds__(512,1) fps_tr_kernel(const float* __restrict__ p1,
                                                       const float* __restrict__ x1,
                                                       float* __restrict__ out_p2)
{
    extern __shared__ char sraw[];
    const int tid = threadIdx.x;

    if (blockIdx.x >= BB) {
        // ---- transpose tile: [B,C,N] -> [B,N,C] ----
        float (*t)[33] = (float (*)[33])sraw;
        int tI = blockIdx.x - BB;
        if (tI == 0 && tid < 2*COUT) {        // fold stat zeroing in (runs before gemm1)
            d_s1[tid] = 0.f; d_s2[tid] = 0.f;
        }
        int b   = tI >> 8;
        int rem = tI & 255;
        int c0  = (rem >> 7) << 5;       // 0 or 32
        int n0  = (rem & 127) << 5;
        int tx = tid & 31, ty = tid >> 5;    // ty 0..15
        #pragma unroll
        for (int i = 0; i < 32; i += 16)
            t[ty+i][tx] = x1[((size_t)b*CIN + c0+ty+i)*NN + n0 + tx];
        __syncthreads();
        #pragma unroll
        for (int i = 0; i < 32; i += 16)
            d_xt[((size_t)b*NN + n0+ty+i)*CIN + c0 + tx] = t[tx][ty+i];
        return;
    }

    // ---- FPS: 512 threads, 8 points/thread (4 packed pairs) ----
    ull*   wkey = (ull*)sraw;                 // 16 per-warp keys
    float* px = (float*)(sraw + 192);
    float* py = px + NN;
    float* pz = py + NN;
    int*   sidx = (int*)(pz + NN);

    const int b = blockIdx.x;
    const int lane = tid & 31, wid = tid >> 5;
    const float* pb = p1 + (size_t)b*NN*3;

    for (int i = tid; i < NN; i += 512) {
        px[i] = pb[3*i+0]; py[i] = pb[3*i+1]; pz[i] = pb[3*i+2];
    }
    __syncthreads();

    ull rx2[4], ry2[4], rz2[4];
    float dist[8];
    #pragma unroll
    for (int pp = 0; pp < 4; pp++) {
        int j0 = tid + ((2*pp  ) << 9);
        int j1 = tid + ((2*pp+1) << 9);
        PACK2(rx2[pp], px[j0], px[j1]);
        PACK2(ry2[pp], py[j0], py[j1]);
        PACK2(rz2[pp], pz[j0], pz[j1]);
        dist[2*pp] = 1e10f; dist[2*pp+1] = 1e10f;
    }

    int far = 0;
    for (int it = 0; it < MM; ++it) {
        if (tid == 0) sidx[it] = far;
        float cx = px[far], cy = py[far], cz = pz[far];
        ull ncx2, ncy2, ncz2;
        { float nx = -cx, ny = -cy, nz = -cz;
          PACK2(ncx2, nx, nx); PACK2(ncy2, ny, ny); PACK2(ncz2, nz, nz); }

        #pragma unroll
        for (int pp = 0; pp < 4; pp++) {
            ull dx, dy, dz, dd;
            ADD2(dx, rx2[pp], ncx2);
            ADD2(dy, ry2[pp], ncy2);
            ADD2(dz, rz2[pp], ncz2);
            MUL2(dd, dz, dz);
            FMA2(dd, dy, dy);
            FMA2(dd, dx, dx);
            float d0, d1; UNPACK2(d0, d1, dd);
            dist[2*pp]   = fminf(dist[2*pp],   d0);
            dist[2*pp+1] = fminf(dist[2*pp+1], d1);
        }

        // per-thread argmax (first-index tie-break: earlier q wins)
        float bd = dist[0]; int bi = tid;
        #pragma unroll
        for (int q = 1; q < 8; q++)
            if (dist[q] > bd) { bd = dist[q]; bi = tid + (q<<9); }

        unsigned bku = __float_as_uint(bd);
        unsigned mk  = __reduce_max_sync(0xffffffffu, bku);
        unsigned cnd = (bku == mk) ? (unsigned)bi : 0xffffffffu;
        unsigned mi  = __reduce_min_sync(0xffffffffu, cnd);
        if (lane == 0)
            wkey[wid] = ((ull)mk << 32) | (unsigned)(~mi);
        __syncthreads();

        // cross-warp: 16 keys -> REDUX max on hi (dist bits), then masked
        // REDUX max on lo (~idx => min index tie-break). ~2x30 cyc vs 8 SHFLs.
        ull k = wkey[lane & 15];
        unsigned hi = (unsigned)(k >> 32);
        unsigned lo = (unsigned)k;
        unsigned mh = __reduce_max_sync(0xffffffffu, hi);
        unsigned cl = (hi == mh) ? lo : 0u;
        unsigned ml = __reduce_max_sync(0xffffffffu, cl);
        far = (int)(~ml);
    }
    __syncthreads();
    for (int m = tid; m < MM; m += 512) {
        int j = sidx[m];
        float x = px[j], y = py[j], z = pz[j];
        size_t o = ((size_t)b*MM + m)*3;
        d_p2[o+0] = x; d_p2[o+1] = y; d_p2[o+2] = z;
        out_p2[o+0] = x; out_p2[o+1] = y; out_p2[o+2] = z;
    }
}

// ---------------- KNN part: top-16 within a 512-point chunk, 2 queries/thr --
#define NCHK 512
#define KNN_SMEM (NCHK*32)

#define KNN_INSERT(d2v, idv, bd, bi)                                   \
    if ((d2v) < bd[KNB-1]) {                                           \
        bd[KNB-1] = (d2v); bi[KNB-1] = (idv);                          \
        _Pragma("unroll")                                              \
        for (int t = KNB-1; t > 0; --t) {                              \
            if (bd[t] < bd[t-1]) {                                     \
                float td = bd[t]; bd[t] = bd[t-1]; bd[t-1] = td;       \
                int   ti = bi[t]; bi[t] = bi[t-1]; bi[t-1] = ti;       \
            }                                                          \
        }                                                              \
    }

__global__ void __launch_bounds__(256) knn_part_kernel(const float* __restrict__ p1)
{
    extern __shared__ ull pn2[];           // [NCHK][4] : (xx, yy, zz, ww)
    const int b = blockIdx.y, tid = threadIdx.x;
    const int ch = blockIdx.x & 7;            // point chunk (0..7)
    const int qg = blockIdx.x >> 3;           // query group (0..1)
    const float* pb = p1 + (size_t)b*NN*3;

    for (int i = tid; i < NCHK; i += 256) {
        int g = ch*NCHK + i;
        float x = pb[3*g], y = pb[3*g+1], z = pb[3*g+2];
        float n1 = (x*x + y*y) + z*z;
        if (x == 0.f && y == 0.f && z == 0.f) n1 = __int_as_float(0x7f800000);
        ull xx, yy, zz, ww;
        PACK2(xx, x, x); PACK2(yy, y, y); PACK2(zz, z, z); PACK2(ww, n1, n1);
        pn2[i*4+0] = xx; pn2[i*4+1] = yy; pn2[i*4+2] = zz; pn2[i*4+3] = ww;
    }
    __syncthreads();

    const int m0 = qg*512 + tid;
    const int m1 = m0 + 256;
    size_t q0o = ((size_t)b*MM + m0)*3;
    size_t q1o = ((size_t)b*MM + m1)*3;
    float q0x = d_p2[q0o], q0y = d_p2[q0o+1], q0z = d_p2[q0o+2];
    float q1x = d_p2[q1o], q1y = d_p2[q1o+1], q1z = d_p2[q1o+2];
    float n20 = (q0x*q0x + q0y*q0y) + q0z*q0z;
    float n21 = (q1x*q1x + q1y*q1y) + q1z*q1z;

    ull qx01, qy01, qz01, n201, m2d;
    PACK2(qx01, q0x, q1x); PACK2(qy01, q0y, q1y); PACK2(qz01, q0z, q1z);
    PACK2(n201, n20, n21);
    { float m2 = -2.f; PACK2(m2d, m2, m2); }

    float bd0[KNB], bd1[KNB]; int bi0[KNB], bi1[KNB];
    #pragma unroll
    for (int t = 0; t < KNB; t++) {
        bd0[t] = 3.4e38f; bi0[t] = 0;
        bd1[t] = 3.4e38f; bi1[t] = 0;
    }

    #pragma unroll 4
    for (int j = 0; j < NCHK; j++) {
        const ulonglong2* pj = (const ulonglong2*)&pn2[j*4];
        ulonglong2 a = pj[0];                 // (xx, yy)
        ulonglong2 c = pj[1];                 // (zz, ww)
        int id = ch*NCHK + j;
        ull dot, t01, d01;
        MUL2(dot, qx01, a.x);
        FMA2(dot, qy01, a.y);
        FMA2(dot, qz01, c.x);
        ADD2(t01, n201, c.y);                 // n2 + n1
        FMA2O(d01, m2d, dot, t01);            // d2 = n2+n1 - 2 dot
        float d20, d21; UNPACK2(d20, d21, d01);
        KNN_INSERT(d20, id, bd0, bi0);
        KNN_INSERT(d21, id, bd1, bi1);
    }
    size_t base0 = ((size_t)b*MM + m0)*128 + ch*16;
    size_t base1 = ((size_t)b*MM + m1)*128 + ch*16;
    #pragma unroll
    for (int t = 0; t < KNB; t++) {
        d_cd[base0 + t] = bd0[t]; d_ci[base0 + t] = bi0[t];
        d_cd[base1 + t] = bd1[t]; d_ci[base1 + t] = bi1[t];
    }
}

// ---------------- KNN merge: 8 sorted 16-lists -> top 16 --------------------
__global__ void __launch_bounds__(256) knn_merge_kernel()
{
    int qi = blockIdx.x*256 + threadIdx.x;     // 0 .. 16383
    size_t base = (size_t)qi*128;
    float bd[KNB]; int bi[KNB];
    #pragma unroll
    for (int t = 0; t < KNB; t++) { bd[t] = 3.4e38f; bi[t] = 0; }
    for (int e = 0; e < 128; e++) {
        float d = d_cd[base + e];
        if (d < bd[KNB-1]) {
            int id = d_ci[base + e];
            KNN_INSERT(d, id, bd, bi);
        }
    }
    #pragma unroll
    for (int t = 0; t < KNB; t++) d_knn[(size_t)qi*KNB + t] = bi[t];
}

// ---------------- GEMM1: h1 = gather(feats) @ w1^T, + per-channel stats -----
// 512 threads, 128x128 tile, occupancy 2. Thread tile 8 rows x 4 cols with
// row-PAIR packed accumulators (A pairs come straight from k-major smem).
#define G_LD 132
#define G1_SMEM ((LDF*G_LD*2)*4 + 128*4)
__global__ void __launch_bounds__(512,2) gemm1_kernel(const float* __restrict__ w1,
                                                      const float* __restrict__ p1)
{
    extern __shared__ float sm[];
    float* Asm = sm;                        // [68][132]  (k-major)
    float* Bsm = sm + LDF*G_LD;             // [68][132]
    int*   sj  = (int*)(Bsm + LDF*G_LD);    // 128 gathered point idx
    const int tid = threadIdx.x;
    const int r0 = blockIdx.x*128;
    const int b  = r0 >> 14;                // 16384 rows per batch

    if (tid < 128) {
        int r = r0 + tid;
        int j = d_knn[r];
        sj[tid] = j;
        int bm = r >> 4;
        size_t po = ((size_t)b*NN + j)*3;
        size_t qo = (size_t)bm*3;
        Asm[0*G_LD + tid] = p1[po+0] - d_p2[qo+0];
        Asm[1*G_LD + tid] = p1[po+1] - d_p2[qo+1];
        Asm[2*G_LD + tid] = p1[po+2] - d_p2[qo+2];
        Asm[3*G_LD + tid] = 0.f;
    }
    for (int f = tid; f < COUT*LDF; f += 512) {
        int o = f / LDF, c = f - o*LDF;
        float v;
        if (c < 3)       v = w1[o*67 + c];
        else if (c == 3) v = 0.f;
        else             v = w1[o*67 + (c-1)];
        Bsm[c*G_LD + o] = v;
    }
    __syncthreads();

    for (int f = tid; f < 128*16; f += 512) {
        int lr = f >> 4, c4 = f & 15;
        const float4 v = *(const float4*)(d_xt + ((size_t)b*NN + sj[lr])*CIN + c4*4);
        int c = 4 + c4*4;
        Asm[(c+0)*G_LD + lr] = v.x;
        Asm[(c+1)*G_LD + lr] = v.y;
        Asm[(c+2)*G_LD + lr] = v.z;
        Asm[(c+3)*G_LD + lr] = v.w;
    }
    __syncthreads();

    const int tx = tid & 31, ty = tid >> 5;      // tx 0..31 (cols), ty 0..15 (rows)
    const float* Ak = Asm + ty*8;
    const float* Bk = Bsm + tx*4;
    ull acc2[4][4];                              // [row-pair][col]
    #pragma unroll
    for (int i = 0; i < 4; i++)
        #pragma unroll
        for (int j = 0; j < 4; j++) acc2[i][j] = 0ull;

    for (int k = 0; k < LDF; k++) {
        ulonglong2 u0 = *(const ulonglong2*)(Ak + k*G_LD);      // rows 0-3 (2 pairs)
        ulonglong2 u1 = *(const ulonglong2*)(Ak + k*G_LD + 4);  // rows 4-7
        float4 q = *(const float4*)(Bk + k*G_LD);
        ull bp[4];
        PACK2(bp[0], q.x, q.x); PACK2(bp[1], q.y, q.y);
        PACK2(bp[2], q.z, q.z); PACK2(bp[3], q.w, q.w);
        ull au[4] = {u0.x, u0.y, u1.x, u1.y};
        #pragma unroll
        for (int i = 0; i < 4; i++)
            #pragma unroll
            for (int j = 0; j < 4; j++) FMA2(acc2[i][j], au[i], bp[j]);
    }

    float acc[8][4];
    #pragma unroll
    for (int i = 0; i < 4; i++)
        #pragma unroll
        for (int j = 0; j < 4; j++)
            UNPACK2(acc[2*i][j], acc[2*i+1][j], acc2[i][j]);

    #pragma unroll
    for (int i = 0; i < 8; i++) {
        size_t row = (size_t)(r0 + ty*8 + i);
        *(float4*)&d_h1[row*COUT + tx*4] = make_float4(acc[i][0],acc[i][1],acc[i][2],acc[i][3]);
    }

    __syncthreads();
    float* ssum = sm; float* ssq = sm + COUT;
    if (tid < COUT) { ssum[tid] = 0.f; ssq[tid] = 0.f; }
    __syncthreads();
    #pragma unroll
    for (int j = 0; j < 4; j++) {
        float s = 0.f, q = 0.f;
        #pragma unroll
        for (int i = 0; i < 8; i++) { float v = acc[i][j]; s += v; q += v*v; }
        atomicAdd(&ssum[tx*4 + j], s);
        atomicAdd(&ssq [tx*4 + j], q);
    }
    __syncthreads();
    if (tid < COUT) {
        atomicAdd(&d_s1[tid],        ssum[tid]);
        atomicAdd(&d_s1[COUT + tid], ssq[tid]);
    }
}

// ---------------- GEMM2: relu(bn1(h1)) @ w2^T -> stats + max over k ---------
// 512 threads, 128x128 tile, K chunked 2x64, full-B preload, occupancy 2.
#define G2_SMEM ((128*G_LD + 64*G_LD + 2*COUT)*4)
__global__ void __launch_bounds__(512,2) gemm2_kernel(const float* __restrict__ w2,
                                                      const float* __restrict__ g1,
                                                      const float* __restrict__ b1)
{
    extern __shared__ float sm[];
    float* Bsm = sm;                        // [128][132]  full B, k-major
    float* Asm = sm + 128*G_LD;             // [64][132]   A chunk, k-major
    float* alp = Asm + 64*G_LD;
    float* bet = alp + COUT;
    const int tid = threadIdx.x;

    if (tid < COUT) {
        float mean = d_s1[tid] * (1.f/RR);
        float var  = d_s1[COUT+tid] * (1.f/RR) - mean*mean;
        float al = g1[tid] * rsqrtf(var + EPSV);
        alp[tid] = al;
        bet[tid] = b1[tid] - al*mean;
    }
    // B full: w2[o][c] k-major (no sync needed against alp/bet: disjoint smem)
    for (int f = tid; f < 128*32; f += 512) {
        int o = f >> 5, c4 = (f & 31)*4;
        float4 w = *(const float4*)&w2[o*128 + c4];
        Bsm[(c4+0)*G_LD + o] = w.x;
        Bsm[(c4+1)*G_LD + o] = w.y;
        Bsm[(c4+2)*G_LD + o] = w.z;
        Bsm[(c4+3)*G_LD + o] = w.w;
    }
    __syncthreads();

    const int r0 = blockIdx.x*128;
    const int tx = tid & 31, ty = tid >> 5;
    const float* Ak = Asm + ty*8;
    const float* Bk = Bsm + tx*4;
    ull acc2[4][4];
    #pragma unroll
    for (int i = 0; i < 4; i++)
        #pragma unroll
        for (int j = 0; j < 4; j++) acc2[i][j] = 0ull;

    for (int kc = 0; kc < 2; kc++) {
        if (kc) __syncthreads();                       // protect A smem reuse
        // A chunk: relu(bn1(h1[r0..r0+127][kc*64 .. +63])) stored k-major
        for (int f = tid; f < 128*16; f += 512) {
            int lr = f >> 4, c4 = (f & 15)*4;
            int c = kc*64 + c4;
            float4 v = *(const float4*)&d_h1[(size_t)(r0+lr)*COUT + c];
            v.x = fmaxf(fmaf(alp[c+0], v.x, bet[c+0]), 0.f);
            v.y = fmaxf(fmaf(alp[c+1], v.y, bet[c+1]), 0.f);
            v.z = fmaxf(fmaf(alp[c+2], v.z, bet[c+2]), 0.f);
            v.w = fmaxf(fmaf(alp[c+3], v.w, bet[c+3]), 0.f);
            Asm[(c4+0)*G_LD + lr] = v.x;
            Asm[(c4+1)*G_LD + lr] = v.y;
            Asm[(c4+2)*G_LD + lr] = v.z;
            Asm[(c4+3)*G_LD + lr] = v.w;
        }
        __syncthreads();

        const float* Bkc = Bk + kc*64*G_LD;
        for (int k = 0; k < 64; k++) {
            ulonglong2 u0 = *(const ulonglong2*)(Ak + k*G_LD);
            ulonglong2 u1 = *(const ulonglong2*)(Ak + k*G_LD + 4);
            float4 q = *(const float4*)(Bkc + k*G_LD);
            ull bp[4];
            PACK2(bp[0], q.x, q.x); PACK2(bp[1], q.y, q.y);
            PACK2(bp[2], q.z, q.z); PACK2(bp[3], q.w, q.w);
            ull au[4] = {u0.x, u0.y, u1.x, u1.y};
            #pragma unroll
            for (int i = 0; i < 4; i++)
                #pragma unroll
                for (int j = 0; j < 4; j++) FMA2(acc2[i][j], au[i], bp[j]);
        }
    }

    float acc[8][4];
    #pragma unroll
    for (int i = 0; i < 4; i++)
        #pragma unroll
        for (int j = 0; j < 4; j++)
            UNPACK2(acc[2*i][j], acc[2*i+1][j], acc2[i][j]);

    // epilogue: per-(b,m) max + channel stats. No h2 store.
    __syncthreads();
    float* mxb  = sm;               // [8][128]
    float* ssum = sm + 1024;
    float* ssq  = ssum + COUT;
    if (tid < COUT) { ssum[tid] = 0.f; ssq[tid] = 0.f; }

    float vmax[4];
    #pragma unroll
    for (int j = 0; j < 4; j++) {
        float m = acc[0][j];
        #pragma unroll
        for (int i = 1; i < 8; i++) m = fmaxf(m, acc[i][j]);
        vmax[j] = m;
    }
    const int g = ty >> 1;                          // local bm group (0..7)
    if ((ty & 1) == 0) {
        #pragma unroll
        for (int j = 0; j < 4; j++) mxb[g*COUT + tx*4 + j] = vmax[j];
    }
    __syncthreads();
    if (ty & 1) {
        int bm = (r0 >> 4) + g;
        #pragma unroll
        for (int j = 0; j < 4; j++) {
            float m = fmaxf(mxb[g*COUT + tx*4 + j], vmax[j]);
            d_mx[(size_t)bm*COUT + tx*4 + j] = m;
        }
    }
    #pragma unroll
    for (int j = 0; j < 4; j++) {
        float s = 0.f, q = 0.f;
        #pragma unroll
        for (int i = 0; i < 8; i++) { float v = acc[i][j]; s += v; q += v*v; }
        atomicAdd(&ssum[tx*4 + j], s);
        atomicAdd(&ssq [tx*4 + j], q);
    }
    __syncthreads();
    if (tid < COUT) {
        atomicAdd(&d_s2[tid],        ssum[tid]);
        atomicAdd(&d_s2[COUT + tid], ssq[tid]);
    }
}

// ---------------- BN2 + ReLU on maxed values, transposed write --------------
__global__ void __launch_bounds__(COUT) final_kernel(const float* __restrict__ g2,
                                                     const float* __restrict__ b2,
                                                     float* __restrict__ outf)
{
    const int o = threadIdx.x;
    const int b = blockIdx.y, m0 = blockIdx.x*32;
    float mean = d_s2[o] * (1.f/RR);
    float var  = d_s2[COUT+o] * (1.f/RR) - mean*mean;
    float al = g2[o] * rsqrtf(var + EPSV);
    float be = b2[o] - al*mean;

    float ov[32];
    #pragma unroll
    for (int mm = 0; mm < 32; ++mm) {
        float v = d_mx[((size_t)(b*MM + m0 + mm))*COUT + o];
        ov[mm] = fmaxf(fmaf(al, v, be), 0.f);
    }
    float* orow = outf + ((size_t)b*COUT + o)*MM + m0;
    #pragma unroll
    for (int q = 0; q < 8; q++)
        ((float4*)orow)[q] = make_float4(ov[4*q], ov[4*q+1], ov[4*q+2], ov[4*q+3]);
}

// ---------------- launch ----------------------------------------------------
extern "C" void kernel_launch(void* const* d_in, const int* in_sizes, int n_in,
                              void* d_out, int out_size)
{
    const float* p1 = (const float*)d_in[0];
    const float* x1 = (const float*)d_in[1];
    const float* w1 = (const float*)d_in[2];
    const float* g1 = (const float*)d_in[3];
    const float* b1 = (const float*)d_in[4];
    const float* w2 = (const float*)d_in[5];
    const float* g2 = (const float*)d_in[6];
    const float* b2 = (const float*)d_in[7];
    float* out = (float*)d_out;

    cudaFuncSetAttribute(fps_tr_kernel,   cudaFuncAttributeMaxDynamicSharedMemorySize, FPS_SMEM);
    cudaFuncSetAttribute(knn_part_kernel, cudaFuncAttributeMaxDynamicSharedMemorySize, KNN_SMEM);
    cudaFuncSetAttribute(gemm1_kernel,    cudaFuncAttributeMaxDynamicSharedMemorySize, G1_SMEM);
    cudaFuncSetAttribute(gemm2_kernel,    cudaFuncAttributeMaxDynamicSharedMemorySize, G2_SMEM);

    fps_tr_kernel<<<BB + BB*2*128, 512, FPS_SMEM>>>(p1, x1, out);
    knn_part_kernel<<<dim3(16, BB), 256, KNN_SMEM>>>(p1);
    knn_merge_kernel<<<(BB*MM)/256, 256>>>();
    gemm1_kernel<<<RR/128, 512, G1_SMEM>>>(w1, p1);
    gemm2_kernel<<<RR/128, 512, G2_SMEM>>>(w2, g1, b1);
    final_kernel<<<dim3(MM/32, BB), COUT>>>(g2, b2, out + (size_t)BB*MM*3);
}